// round 1
// baseline (speedup 1.0000x reference)
#include <cuda_runtime.h>

#define NN 100000
#define NE 1600000
#define HID 128
#define NG 64
#define NC 10

// Persistent scratch (static __device__ arrays — no runtime allocation).
__device__ float4 g_h1v[NN * HID / 4];
__device__ float4 g_h2v[NN * HID / 4];
__device__ float4 g_aggv[NN * HID / 4];
__device__ float g_cnt[NN];
__device__ float g_inv[NN];
__device__ float g_aggx[NN];
__device__ float g_pool[NG * HID];
__device__ float g_gcnt[NG];

// ---------------------------------------------------------------------------
// Degree count + scalar (dim=1) neighbor aggregation for layer 1
// ---------------------------------------------------------------------------
__global__ void k_edge_scalar(const float* __restrict__ x,
                              const int* __restrict__ ei, int E) {
    int e = blockIdx.x * blockDim.x + threadIdx.x;
    if (e < E) {
        int s = ei[e];
        int d = ei[E + e];
        atomicAdd(&g_cnt[d], 1.0f);
        atomicAdd(&g_aggx[d], __ldg(&x[s]));
    }
}

__global__ void k_inv(int N) {
    int n = blockIdx.x * blockDim.x + threadIdx.x;
    if (n < N) g_inv[n] = 1.0f / fmaxf(g_cnt[n], 1.0f);
}

// Graph-size counts with run-length compression (batch is sorted).
__global__ void k_gcnt(const int* __restrict__ batch, int N) {
    int t = blockIdx.x * blockDim.x + threadIdx.x;
    int n0 = t * 32;
    if (n0 >= N) return;
    int ne = min(n0 + 32, N);
    int cur = batch[n0];
    float c = 0.0f;
    for (int n = n0; n < ne; n++) {
        int b = batch[n];
        if (b != cur) { atomicAdd(&g_gcnt[cur], c); c = 0.0f; cur = b; }
        c += 1.0f;
    }
    atomicAdd(&g_gcnt[cur], c);
}

// ---------------------------------------------------------------------------
// Layer 1: h1[n][j] = relu(mean_n * W1l[j] + b1[j] + x[n] * W1r[j])
// ---------------------------------------------------------------------------
__global__ void k_layer1(const float* __restrict__ x,
                         const float* __restrict__ W1l,
                         const float* __restrict__ W1r,
                         const float* __restrict__ b1, int N) {
    int i = blockIdx.x * blockDim.x + threadIdx.x;
    if (i < N * HID) {
        int n = i >> 7;
        int j = i & 127;
        float mean = g_aggx[n] * g_inv[n];
        float v = fmaf(mean, __ldg(&W1l[j]), __ldg(&b1[j]));
        v = fmaf(__ldg(&x[n]), __ldg(&W1r[j]), v);
        ((float*)g_h1v)[i] = fmaxf(v, 0.0f);
    }
}

// ---------------------------------------------------------------------------
// 128-wide edge aggregation: one warp per edge, RED.128 scatter-add
// ---------------------------------------------------------------------------
__global__ void k_scatter(const float* __restrict__ h,
                          const int* __restrict__ ei, int E) {
    int gt = blockIdx.x * blockDim.x + threadIdx.x;
    int w = gt >> 5;
    int lane = gt & 31;
    if (w < E) {
        int s = ei[w];
        int d = ei[E + w];
        float4 v = __ldg((const float4*)(h + (size_t)s * HID) + lane);
        float* a = ((float*)g_aggv) + (size_t)d * HID + lane * 4;
        asm volatile("red.global.add.v4.f32 [%0], {%1,%2,%3,%4};"
                     :: "l"(a), "f"(v.x), "f"(v.y), "f"(v.z), "f"(v.w)
                     : "memory");
    }
}

// ---------------------------------------------------------------------------
// Fused SAGE layer: hout[n][:] = relu( (agg[n]/cnt[n]) @ Wl + hin[n] @ Wr + b )
// 128-node tiles, 256 threads, 8x8 register tiles, 128KB dynamic smem.
// ---------------------------------------------------------------------------
__global__ __launch_bounds__(256, 1)
void k_sage(const float* __restrict__ hin, float* __restrict__ hout,
            const float* __restrict__ Wl, const float* __restrict__ Wr,
            const float* __restrict__ bias, int N) {
    extern __shared__ float sm[];
    float* Ws = sm;              // [128][128]
    float* Is = sm + HID * HID;  // [128][128]

    int tid = threadIdx.x;
    int n0 = blockIdx.x * 128;
    int tx = tid & 15;   // col group
    int ty = tid >> 4;   // row group
    int c0 = tx * 8;
    int r0 = ty * 8;

    float acc[8][8];
#pragma unroll
    for (int i = 0; i < 8; i++)
#pragma unroll
        for (int j = 0; j < 8; j++) acc[i][j] = 0.0f;

    const float* aggf = (const float*)g_aggv;

    for (int p = 0; p < 2; p++) {
        const float* W = p ? Wr : Wl;
        const float* src = p ? hin : aggf;

        // Load weights (4096 float4, coalesced)
#pragma unroll
        for (int m = 0; m < 16; m++) {
            int idx = tid + m * 256;
            ((float4*)Ws)[idx] = __ldg((const float4*)W + idx);
        }
        // Load input tile (row-major), scaling neighbor part by 1/cnt
#pragma unroll
        for (int m = 0; m < 16; m++) {
            int idx = tid + m * 256;
            int row = idx >> 5;
            int gr = n0 + row;
            float4 v = make_float4(0.f, 0.f, 0.f, 0.f);
            if (gr < N) {
                v = __ldg((const float4*)(src + (size_t)gr * HID) + (idx & 31));
                if (p == 0) {
                    float s = g_inv[gr];
                    v.x *= s; v.y *= s; v.z *= s; v.w *= s;
                }
            }
            ((float4*)Is)[idx] = v;
        }
        __syncthreads();

#pragma unroll 4
        for (int k = 0; k < HID; k++) {
            float a[8];
#pragma unroll
            for (int i = 0; i < 8; i++) a[i] = Is[(r0 + i) * HID + k];
            float4 w0 = *(const float4*)&Ws[k * HID + c0];
            float4 w1 = *(const float4*)&Ws[k * HID + c0 + 4];
            float wv[8] = {w0.x, w0.y, w0.z, w0.w, w1.x, w1.y, w1.z, w1.w};
#pragma unroll
            for (int i = 0; i < 8; i++)
#pragma unroll
                for (int j = 0; j < 8; j++)
                    acc[i][j] = fmaf(a[i], wv[j], acc[i][j]);
        }
        __syncthreads();
    }

    float4 bv0 = __ldg((const float4*)&bias[c0]);
    float4 bv1 = __ldg((const float4*)&bias[c0 + 4]);
    float bb[8] = {bv0.x, bv0.y, bv0.z, bv0.w, bv1.x, bv1.y, bv1.z, bv1.w};
#pragma unroll
    for (int i = 0; i < 8; i++) {
        int gr = n0 + r0 + i;
        if (gr < N) {
            float4 o0, o1;
            o0.x = fmaxf(acc[i][0] + bb[0], 0.f);
            o0.y = fmaxf(acc[i][1] + bb[1], 0.f);
            o0.z = fmaxf(acc[i][2] + bb[2], 0.f);
            o0.w = fmaxf(acc[i][3] + bb[3], 0.f);
            o1.x = fmaxf(acc[i][4] + bb[4], 0.f);
            o1.y = fmaxf(acc[i][5] + bb[5], 0.f);
            o1.z = fmaxf(acc[i][6] + bb[6], 0.f);
            o1.w = fmaxf(acc[i][7] + bb[7], 0.f);
            *(float4*)(hout + (size_t)gr * HID + c0) = o0;
            *(float4*)(hout + (size_t)gr * HID + c0 + 4) = o1;
        }
    }
}

// ---------------------------------------------------------------------------
// Mean pool: run-length compressed atomics (batch sorted); 64 nodes / block
// ---------------------------------------------------------------------------
__global__ void k_pool(const float* __restrict__ h,
                       const int* __restrict__ batch, int N) {
    int j = threadIdx.x;  // 128 threads = one column each
    int n0 = blockIdx.x * 64;
    if (n0 >= N) return;
    int ne = min(n0 + 64, N);
    int cur = batch[n0];
    float acc = 0.0f;
    for (int n = n0; n < ne; n++) {
        int b = batch[n];
        if (b != cur) {
            atomicAdd(&g_pool[cur * HID + j], acc);
            acc = 0.0f;
            cur = b;
        }
        acc += h[(size_t)n * HID + j];
    }
    atomicAdd(&g_pool[cur * HID + j], acc);
}

// ---------------------------------------------------------------------------
// Head: logits = (pool/gcnt) @ Wfc + bfc ; out = log_softmax(logits)
// ---------------------------------------------------------------------------
__global__ void k_head(const float* __restrict__ Wfc,
                       const float* __restrict__ bfc,
                       float* __restrict__ out) {
    __shared__ float lg[NG][NC];
    int t = threadIdx.x;
    if (t < NG * NC) {
        int g = t / NC;
        int c = t % NC;
        float ginv = 1.0f / fmaxf(g_gcnt[g], 1.0f);
        float s = __ldg(&bfc[c]);
        for (int k = 0; k < HID; k++)
            s = fmaf(g_pool[g * HID + k] * ginv, __ldg(&Wfc[k * NC + c]), s);
        lg[g][c] = s;
    }
    __syncthreads();
    if (t < NG) {
        float m = -1e30f;
        for (int c = 0; c < NC; c++) m = fmaxf(m, lg[t][c]);
        float se = 0.0f;
        for (int c = 0; c < NC; c++) se += expf(lg[t][c] - m);
        float lse = m + logf(se);
        for (int c = 0; c < NC; c++) out[t * NC + c] = lg[t][c] - lse;
    }
}

// ---------------------------------------------------------------------------
extern "C" void kernel_launch(void* const* d_in, const int* in_sizes, int n_in,
                              void* d_out, int out_size) {
    const float* x   = (const float*)d_in[0];
    const int* ei    = (const int*)d_in[1];
    const int* batch = (const int*)d_in[2];
    const float* W1l = (const float*)d_in[3];
    const float* W1r = (const float*)d_in[4];
    const float* b1  = (const float*)d_in[5];
    const float* W2l = (const float*)d_in[6];
    const float* W2r = (const float*)d_in[7];
    const float* b2  = (const float*)d_in[8];
    const float* W3l = (const float*)d_in[9];
    const float* W3r = (const float*)d_in[10];
    const float* b3  = (const float*)d_in[11];
    const float* Wfc = (const float*)d_in[12];
    const float* bfc = (const float*)d_in[13];
    float* out = (float*)d_out;

    int N = in_sizes[0];
    int E = in_sizes[1] / 2;

    void *p_cnt, *p_aggx, *p_gcnt, *p_pool, *p_agg, *p_h1, *p_h2;
    cudaGetSymbolAddress(&p_cnt, g_cnt);
    cudaGetSymbolAddress(&p_aggx, g_aggx);
    cudaGetSymbolAddress(&p_gcnt, g_gcnt);
    cudaGetSymbolAddress(&p_pool, g_pool);
    cudaGetSymbolAddress(&p_agg, g_aggv);
    cudaGetSymbolAddress(&p_h1, g_h1v);
    cudaGetSymbolAddress(&p_h2, g_h2v);

    const int SMEM = 2 * HID * HID * (int)sizeof(float);  // 128 KB
    cudaFuncSetAttribute(k_sage, cudaFuncAttributeMaxDynamicSharedMemorySize, SMEM);

    cudaMemsetAsync(p_cnt, 0, (size_t)N * 4);
    cudaMemsetAsync(p_aggx, 0, (size_t)N * 4);
    cudaMemsetAsync(p_gcnt, 0, NG * 4);
    cudaMemsetAsync(p_pool, 0, NG * HID * 4);

    k_edge_scalar<<<(E + 255) / 256, 256>>>(x, ei, E);
    k_inv<<<(N + 255) / 256, 256>>>(N);
    k_gcnt<<<((N + 31) / 32 + 255) / 256, 256>>>(batch, N);
    k_layer1<<<(N * HID + 255) / 256, 256>>>(x, W1l, W1r, b1, N);

    int sage_blocks = (N + 127) / 128;
    long long sth = (long long)E * 32;
    int sblocks = (int)((sth + 255) / 256);

    // Layer 2
    cudaMemsetAsync(p_agg, 0, (size_t)N * HID * 4);
    k_scatter<<<sblocks, 256>>>((const float*)p_h1, ei, E);
    k_sage<<<sage_blocks, 256, SMEM>>>((const float*)p_h1, (float*)p_h2, W2l, W2r, b2, N);

    // Layer 3
    cudaMemsetAsync(p_agg, 0, (size_t)N * HID * 4);
    k_scatter<<<sblocks, 256>>>((const float*)p_h2, ei, E);
    k_sage<<<sage_blocks, 256, SMEM>>>((const float*)p_h2, (float*)p_h1, W3l, W3r, b3, N);

    // Pool + head
    k_pool<<<(N + 63) / 64, 128>>>((const float*)p_h1, batch, N);
    k_head<<<1, 640>>>(Wfc, bfc, out);
}

// round 3
// speedup vs baseline: 1.2949x; 1.2949x over previous
#include <cuda_runtime.h>
#include <cuda_bf16.h>
#include <cstdint>

#define NN 100000
#define NE 1600000
#define HID 128
#define NG 64
#define NC 10

// ---------------------------------------------------------------------------
// Persistent scratch (static __device__ arrays — no runtime allocation).
// ---------------------------------------------------------------------------
__device__ float4 g_h1v[NN * HID / 4];
__device__ float4 g_h2v[NN * HID / 4];
__device__ float4 g_aggv[NN * HID / 4];
__device__ float g_inv[NN];
__device__ float g_aggx[NN];
__device__ float g_pool[NG * HID];
__device__ float g_gcnt[NG];
// CSR
__device__ int g_deg[NN];
__device__ int g_rowptr[NN + 1];
__device__ int g_cursor[NN];
__device__ int g_csrc[NE];
__device__ int g_bsum[512];
__device__ int g_boff[512];
// Pre-split B chunk images: 2 layers x 8 chunks x [64 k][136 n(pad)] bf16
// chunk u32 count = 17408/4 = 4352 ; row stride = 272B = 68 u32
__device__ uint32_t g_Bp[2 * 8 * 4352];

// ---------------------------------------------------------------------------
// Helpers
// ---------------------------------------------------------------------------
__device__ __forceinline__ uint32_t smem_u32(const void* p) {
    uint32_t a;
    asm("{ .reg .u64 t; cvta.to.shared.u64 t, %1; cvt.u32.u64 %0, t; }"
        : "=r"(a) : "l"(p));
    return a;
}

__device__ __forceinline__ uint32_t pack_bf16x2(__nv_bfloat16 lo, __nv_bfloat16 hi) {
    return ((uint32_t)__bfloat16_as_ushort(hi) << 16) | __bfloat16_as_ushort(lo);
}

__device__ __forceinline__ void ldmatrix_x4(uint32_t r[4], uint32_t addr) {
    asm volatile("ldmatrix.sync.aligned.m8n8.x4.shared.b16 {%0,%1,%2,%3}, [%4];"
                 : "=r"(r[0]), "=r"(r[1]), "=r"(r[2]), "=r"(r[3]) : "r"(addr));
}

__device__ __forceinline__ void ldmatrix_x2t(uint32_t& b0, uint32_t& b1, uint32_t addr) {
    asm volatile("ldmatrix.sync.aligned.m8n8.x2.trans.shared.b16 {%0,%1}, [%2];"
                 : "=r"(b0), "=r"(b1) : "r"(addr));
}

__device__ __forceinline__ void mma_bf16(float d[4], const uint32_t a[4],
                                         uint32_t b0, uint32_t b1) {
    asm volatile(
        "mma.sync.aligned.m16n8k16.row.col.f32.bf16.bf16.f32 "
        "{%0,%1,%2,%3}, {%4,%5,%6,%7}, {%8,%9}, {%0,%1,%2,%3};"
        : "+f"(d[0]), "+f"(d[1]), "+f"(d[2]), "+f"(d[3])
        : "r"(a[0]), "r"(a[1]), "r"(a[2]), "r"(a[3]), "r"(b0), "r"(b1));
}

// ---------------------------------------------------------------------------
// CSR build: degree histogram -> scan -> fill
// ---------------------------------------------------------------------------
__global__ void k_deg(const int* __restrict__ ei, int E) {
    int e = blockIdx.x * blockDim.x + threadIdx.x;
    if (e < E) atomicAdd(&g_deg[ei[E + e]], 1);
}

__global__ void k_scan1(int N) {
    __shared__ int s[256];
    int idx = blockIdx.x * 256 + threadIdx.x;
    int v = (idx < N) ? g_deg[idx] : 0;
    s[threadIdx.x] = v;
    __syncthreads();
    for (int off = 128; off > 0; off >>= 1) {
        if (threadIdx.x < off) s[threadIdx.x] += s[threadIdx.x + off];
        __syncthreads();
    }
    if (threadIdx.x == 0) g_bsum[blockIdx.x] = s[0];
}

__global__ void k_scan2(int nb, int E) {
    if (threadIdx.x == 0) {
        int run = 0;
        for (int i = 0; i < nb; i++) { g_boff[i] = run; run += g_bsum[i]; }
        g_rowptr[NN] = E;
    }
}

__global__ void k_scan3(int N) {
    __shared__ int s[256];
    int t = threadIdx.x;
    int idx = blockIdx.x * 256 + t;
    int v = (idx < N) ? g_deg[idx] : 0;
    s[t] = v;
    __syncthreads();
#pragma unroll
    for (int off = 1; off < 256; off <<= 1) {
        int add = (t >= off) ? s[t - off] : 0;
        __syncthreads();
        s[t] += add;
        __syncthreads();
    }
    if (idx < N) {
        int ex = s[t] - v + g_boff[blockIdx.x];
        g_rowptr[idx] = ex;
        g_cursor[idx] = ex;
    }
}

__global__ void k_fill(const int* __restrict__ ei, int E) {
    int e = blockIdx.x * blockDim.x + threadIdx.x;
    if (e < E) {
        int s = ei[e];
        int d = ei[E + e];
        int pos = atomicAdd(&g_cursor[d], 1);
        g_csrc[pos] = s;
    }
}

// ---------------------------------------------------------------------------
// Scalar aggregation for layer 1 + inverse degree
// ---------------------------------------------------------------------------
__global__ void k_aggx(const float* __restrict__ x, int N) {
    int n = blockIdx.x * blockDim.x + threadIdx.x;
    if (n < N) {
        int beg = g_rowptr[n], end = g_rowptr[n + 1];
        float s = 0.0f;
        for (int i = beg; i < end; i++) s += __ldg(&x[g_csrc[i]]);
        g_aggx[n] = s;
        g_inv[n] = 1.0f / fmaxf((float)(end - beg), 1.0f);
    }
}

__global__ void k_gcnt(const int* __restrict__ batch, int N) {
    int t = blockIdx.x * blockDim.x + threadIdx.x;
    int n0 = t * 32;
    if (n0 >= N) return;
    int ne = min(n0 + 32, N);
    int cur = batch[n0];
    float c = 0.0f;
    for (int n = n0; n < ne; n++) {
        int b = batch[n];
        if (b != cur) { atomicAdd(&g_gcnt[cur], c); c = 0.0f; cur = b; }
        c += 1.0f;
    }
    atomicAdd(&g_gcnt[cur], c);
}

// ---------------------------------------------------------------------------
// Layer 1 (exact fp32, rank-2)
// ---------------------------------------------------------------------------
__global__ void k_layer1(const float* __restrict__ x,
                         const float* __restrict__ W1l,
                         const float* __restrict__ W1r,
                         const float* __restrict__ b1, int N) {
    int i = blockIdx.x * blockDim.x + threadIdx.x;
    if (i < N * HID) {
        int n = i >> 7;
        int j = i & 127;
        float mean = g_aggx[n] * g_inv[n];
        float v = fmaf(mean, __ldg(&W1l[j]), __ldg(&b1[j]));
        v = fmaf(__ldg(&x[n]), __ldg(&W1r[j]), v);
        ((float*)g_h1v)[i] = fmaxf(v, 0.0f);
    }
}

// ---------------------------------------------------------------------------
// CSR gather aggregation (128-wide): one warp per dst node, pure reads
// ---------------------------------------------------------------------------
__global__ void k_gather(const float* __restrict__ h, int N) {
    int gt = blockIdx.x * blockDim.x + threadIdx.x;
    int node = gt >> 5;
    int lane = gt & 31;
    if (node >= N) return;
    int beg = g_rowptr[node], end = g_rowptr[node + 1];
    float4 a = make_float4(0.f, 0.f, 0.f, 0.f);
    int i = beg;
    for (; i + 1 < end; i += 2) {
        int s0 = g_csrc[i], s1 = g_csrc[i + 1];
        float4 v0 = __ldg((const float4*)(h + (size_t)s0 * HID) + lane);
        float4 v1 = __ldg((const float4*)(h + (size_t)s1 * HID) + lane);
        a.x += v0.x + v1.x; a.y += v0.y + v1.y;
        a.z += v0.z + v1.z; a.w += v0.w + v1.w;
    }
    if (i < end) {
        int s0 = g_csrc[i];
        float4 v0 = __ldg((const float4*)(h + (size_t)s0 * HID) + lane);
        a.x += v0.x; a.y += v0.y; a.z += v0.z; a.w += v0.w;
    }
    g_aggv[(size_t)node * 32 + lane] = a;
}

// ---------------------------------------------------------------------------
// Weight prep: B chunk images [64 k][136 n(pad)] bf16 per chunk.
// chunks 0-3 = Bh (K 0..255), 4-7 = Bl. W'[k][n]: k<128 -> Wl, else Wr.
// ---------------------------------------------------------------------------
__global__ void k_prepB(const float* __restrict__ Wl,
                        const float* __restrict__ Wr, int layer) {
    int t = blockIdx.x * blockDim.x + threadIdx.x;
    if (t >= 8 * 64 * 64) return;
    int ci = t >> 12;
    int rem = t & 4095;
    int k = rem >> 6;
    int np = rem & 63;
    int n = np * 2;
    int kk = (ci & 3) * 64 + k;
    float w0 = (kk < 128) ? Wl[kk * HID + n] : Wr[(kk - 128) * HID + n];
    float w1 = (kk < 128) ? Wl[kk * HID + n + 1] : Wr[(kk - 128) * HID + n + 1];
    __nv_bfloat16 b0, b1;
    if (ci < 4) {
        b0 = __float2bfloat16(w0);
        b1 = __float2bfloat16(w1);
    } else {
        __nv_bfloat16 h0 = __float2bfloat16(w0), h1 = __float2bfloat16(w1);
        b0 = __float2bfloat16(w0 - __bfloat162float(h0));
        b1 = __float2bfloat16(w1 - __bfloat162float(h1));
    }
    g_Bp[layer * 34816 + ci * 4352 + k * 68 + np] = pack_bf16x2(b0, b1);
}

// ---------------------------------------------------------------------------
// Fused SAGE GEMM via mma.sync bf16, 3M split (K_eff = 768):
//   hout = relu( [agg*inv | hin] @ [Wl;Wr] + b )
// Block: 128 rows x 128 cols, 256 threads (8 warps, 4 row-groups x 2 col-groups)
// smem: Ah[128][264] bf16 (67584B) | Al (67584B) | Bchunk [64][136] (17408B)
// ---------------------------------------------------------------------------
#define AP 528          // A row stride bytes (264 bf16, odd 16B-stride -> no conflicts)
#define BP 272          // B row stride bytes (136 bf16)
#define SM_AL 67584
#define SM_B  135168
#define SMEM_GEMM (135168 + 17408)

__global__ __launch_bounds__(256, 1)
void k_gemm(const float* __restrict__ hin, float* __restrict__ hout,
            const float* __restrict__ bias, int layer, int N) {
    extern __shared__ char sm[];
    uint32_t smb = smem_u32(sm);
    int tid = threadIdx.x;
    int lane = tid & 31;
    int wid = tid >> 5;
    int n0 = blockIdx.x * 128;
    const float* aggf = (const float*)g_aggv;

    // --- Stage A: fp32 -> (Ah, Al) bf16 split tiles ---
#pragma unroll 4
    for (int it = 0; it < 64; it++) {
        int idx = tid + it * 256;
        int r = idx >> 7;
        int p = idx & 127;
        int node = n0 + r;
        float2 v = make_float2(0.f, 0.f);
        if (node < N) {
            if (p < 64) {
                v = ((const float2*)(aggf + (size_t)node * HID))[p];
                float s = g_inv[node];
                v.x *= s; v.y *= s;
            } else {
                v = ((const float2*)(hin + (size_t)node * HID))[p - 64];
            }
        }
        __nv_bfloat16 hx = __float2bfloat16(v.x), hy = __float2bfloat16(v.y);
        __nv_bfloat16 gx = __float2bfloat16(v.x - __bfloat162float(hx));
        __nv_bfloat16 gy = __float2bfloat16(v.y - __bfloat162float(hy));
        *(uint32_t*)(sm + r * AP + p * 4) = pack_bf16x2(hx, hy);
        *(uint32_t*)(sm + SM_AL + r * AP + p * 4) = pack_bf16x2(gx, gy);
    }
    __syncthreads();

    float acc[2][8][4];
#pragma unroll
    for (int s = 0; s < 2; s++)
#pragma unroll
        for (int nt = 0; nt < 8; nt++)
#pragma unroll
            for (int q = 0; q < 4; q++) acc[s][nt][q] = 0.0f;

    int wr = wid & 3;
    int wc = wid >> 2;
    const uint32_t* Bpl = g_Bp + layer * 34816;

    int a_r = lane & 15;
    int a_c8 = (lane >> 4) << 3;
    int b_r = lane & 15;

    for (int c = 0; c < 12; c++) {
        int term = c >> 2;
        int kc = c & 3;
        int ci = (term == 2) ? (4 + kc) : kc;
        // cooperative copy of B chunk (17408B = 1088 uint4)
        const uint4* srcB = (const uint4*)(Bpl + ci * 4352);
        uint4* dstB = (uint4*)(sm + SM_B);
#pragma unroll
        for (int m = 0; m < 5; m++) {
            int i = tid + m * 256;
            if (i < 1088) dstB[i] = __ldg(srcB + i);
        }
        __syncthreads();

        uint32_t abase = smb + ((term == 1) ? SM_AL : 0);
        int acol0 = kc * 64;
#pragma unroll
        for (int ks = 0; ks < 4; ks++) {
            int k0 = acol0 + ks * 16;
            uint32_t a0[4], a1[4];
            uint32_t addr0 = abase + (uint32_t)((wr * 32 + a_r) * AP + (k0 + a_c8) * 2);
            ldmatrix_x4(a0, addr0);
            ldmatrix_x4(a1, addr0 + 16 * AP);
            uint32_t bbase = smb + SM_B + (uint32_t)((ks * 16 + b_r) * BP + wc * 128);
#pragma unroll
            for (int nt = 0; nt < 8; nt++) {
                uint32_t b0, b1;
                ldmatrix_x2t(b0, b1, bbase + nt * 16);
                mma_bf16(acc[0][nt], a0, b0, b1);
                mma_bf16(acc[1][nt], a1, b0, b1);
            }
        }
        __syncthreads();
    }

    // --- Epilogue: bias + relu, direct register -> global ---
    int qr = lane >> 2;
    int qc = (lane & 3) * 2;
#pragma unroll
    for (int s = 0; s < 2; s++) {
        int mb = n0 + wr * 32 + s * 16;
#pragma unroll
        for (int nt = 0; nt < 8; nt++) {
            int col = wc * 64 + nt * 8 + qc;
            float2 bv = *(const float2*)(bias + col);
            int mlo = mb + qr;
            int mhi = mlo + 8;
            if (mlo < N) {
                float2 o;
                o.x = fmaxf(acc[s][nt][0] + bv.x, 0.f);
                o.y = fmaxf(acc[s][nt][1] + bv.y, 0.f);
                *(float2*)(hout + (size_t)mlo * HID + col) = o;
            }
            if (mhi < N) {
                float2 o;
                o.x = fmaxf(acc[s][nt][2] + bv.x, 0.f);
                o.y = fmaxf(acc[s][nt][3] + bv.y, 0.f);
                *(float2*)(hout + (size_t)mhi * HID + col) = o;
            }
        }
    }
}

// ---------------------------------------------------------------------------
// Mean pool: run-length compressed atomics (batch sorted)
// ---------------------------------------------------------------------------
__global__ void k_pool(const float* __restrict__ h,
                       const int* __restrict__ batch, int N) {
    int j = threadIdx.x;
    int n0 = blockIdx.x * 64;
    if (n0 >= N) return;
    int ne = min(n0 + 64, N);
    int cur = batch[n0];
    float acc = 0.0f;
    for (int n = n0; n < ne; n++) {
        int b = batch[n];
        if (b != cur) {
            atomicAdd(&g_pool[cur * HID + j], acc);
            acc = 0.0f;
            cur = b;
        }
        acc += h[(size_t)n * HID + j];
    }
    atomicAdd(&g_pool[cur * HID + j], acc);
}

// ---------------------------------------------------------------------------
// Head: logits = (pool/gcnt) @ Wfc + bfc ; log_softmax
// ---------------------------------------------------------------------------
__global__ void k_head(const float* __restrict__ Wfc,
                       const float* __restrict__ bfc,
                       float* __restrict__ out) {
    __shared__ float lg[NG][NC];
    int t = threadIdx.x;
    if (t < NG * NC) {
        int g = t / NC;
        int c = t % NC;
        float ginv = 1.0f / fmaxf(g_gcnt[g], 1.0f);
        float s = __ldg(&bfc[c]);
        for (int k = 0; k < HID; k++)
            s = fmaf(g_pool[g * HID + k] * ginv, __ldg(&Wfc[k * NC + c]), s);
        lg[g][c] = s;
    }
    __syncthreads();
    if (t < NG) {
        float m = -1e30f;
        for (int c = 0; c < NC; c++) m = fmaxf(m, lg[t][c]);
        float se = 0.0f;
        for (int c = 0; c < NC; c++) se += expf(lg[t][c] - m);
        float lse = m + logf(se);
        for (int c = 0; c < NC; c++) out[t * NC + c] = lg[t][c] - lse;
    }
}

// ---------------------------------------------------------------------------
extern "C" void kernel_launch(void* const* d_in, const int* in_sizes, int n_in,
                              void* d_out, int out_size) {
    const float* x   = (const float*)d_in[0];
    const int* ei    = (const int*)d_in[1];
    const int* batch = (const int*)d_in[2];
    const float* W1l = (const float*)d_in[3];
    const float* W1r = (const float*)d_in[4];
    const float* b1  = (const float*)d_in[5];
    const float* W2l = (const float*)d_in[6];
    const float* W2r = (const float*)d_in[7];
    const float* b2  = (const float*)d_in[8];
    const float* W3l = (const float*)d_in[9];
    const float* W3r = (const float*)d_in[10];
    const float* b3  = (const float*)d_in[11];
    const float* Wfc = (const float*)d_in[12];
    const float* bfc = (const float*)d_in[13];
    float* out = (float*)d_out;

    int N = in_sizes[0];
    int E = in_sizes[1] / 2;
    int nb = (N + 255) / 256;

    void *p_deg, *p_gcnt, *p_pool, *p_h1, *p_h2;
    cudaGetSymbolAddress(&p_deg, g_deg);
    cudaGetSymbolAddress(&p_gcnt, g_gcnt);
    cudaGetSymbolAddress(&p_pool, g_pool);
    cudaGetSymbolAddress(&p_h1, g_h1v);
    cudaGetSymbolAddress(&p_h2, g_h2v);

    cudaFuncSetAttribute(k_gemm, cudaFuncAttributeMaxDynamicSharedMemorySize, SMEM_GEMM);

    cudaMemsetAsync(p_deg, 0, (size_t)N * 4);
    cudaMemsetAsync(p_gcnt, 0, NG * 4);
    cudaMemsetAsync(p_pool, 0, NG * HID * 4);

    // CSR build
    k_deg<<<(E + 255) / 256, 256>>>(ei, E);
    k_scan1<<<nb, 256>>>(N);
    k_scan2<<<1, 32>>>(nb, E);
    k_scan3<<<nb, 256>>>(N);
    k_fill<<<(E + 255) / 256, 256>>>(ei, E);

    // Prep + layer 1
    k_aggx<<<(N + 255) / 256, 256>>>(x, N);
    k_gcnt<<<((N + 31) / 32 + 255) / 256, 256>>>(batch, N);
    k_prepB<<<128, 256>>>(W2l, W2r, 0);
    k_prepB<<<128, 256>>>(W3l, W3r, 1);
    k_layer1<<<(N * HID + 255) / 256, 256>>>(x, W1l, W1r, b1, N);

    int gat_blocks = (N * 32 + 255) / 256;
    int gemm_blocks = (N + 127) / 128;

    // Layer 2
    k_gather<<<gat_blocks, 256>>>((const float*)p_h1, N);
    k_gemm<<<gemm_blocks, 256, SMEM_GEMM>>>((const float*)p_h1, (float*)p_h2, b2, 0, N);

    // Layer 3
    k_gather<<<gat_blocks, 256>>>((const float*)p_h2, N);
    k_gemm<<<gemm_blocks, 256, SMEM_GEMM>>>((const float*)p_h2, (float*)p_h1, b3, 1, N);

    // Pool + head
    k_pool<<<(N + 63) / 64, 128>>>((const float*)p_h1, batch, N);
    k_head<<<1, 640>>>(Wfc, bfc, out);
}

// round 5
// speedup vs baseline: 1.7055x; 1.3171x over previous
#include <cuda_runtime.h>
#include <cuda_bf16.h>
#include <cuda_fp16.h>
#include <cstdint>

#define NN 100000
#define NE 1600000
#define HID 128
#define NG 64
#define NC 10

// ---------------------------------------------------------------------------
// Persistent scratch (static __device__ arrays — no runtime allocation).
// ---------------------------------------------------------------------------
__device__ __half g_h1h[NN * HID];     // fp16 activations (ping)
__device__ __half g_h2h[NN * HID];     // fp16 activations (pong)
__device__ float4 g_aggv[NN * HID / 4];
__device__ float g_inv[NN];
__device__ float g_aggx[NN];
__device__ float g_pool[NG * HID];
__device__ float g_gcnt[NG];
// CSR
__device__ int g_deg[NN];
__device__ int g_rowptr[NN + 1];
__device__ int g_cursor[NN];
__device__ int g_csrc[NE];
__device__ int g_bsum[512];
__device__ int g_boff[512];
// Pre-split B chunk images: 2 layers x 8 chunks x [64 k][136 n(pad)] bf16
__device__ uint32_t g_Bp[2 * 8 * 4352];

// ---------------------------------------------------------------------------
// Helpers
// ---------------------------------------------------------------------------
__device__ __forceinline__ uint32_t smem_u32(const void* p) {
    uint32_t a;
    asm("{ .reg .u64 t; cvta.to.shared.u64 t, %1; cvt.u32.u64 %0, t; }"
        : "=r"(a) : "l"(p));
    return a;
}

__device__ __forceinline__ uint32_t pack_bf16x2(__nv_bfloat16 lo, __nv_bfloat16 hi) {
    return ((uint32_t)__bfloat16_as_ushort(hi) << 16) | __bfloat16_as_ushort(lo);
}

__device__ __forceinline__ void ldmatrix_x4(uint32_t r[4], uint32_t addr) {
    asm volatile("ldmatrix.sync.aligned.m8n8.x4.shared.b16 {%0,%1,%2,%3}, [%4];"
                 : "=r"(r[0]), "=r"(r[1]), "=r"(r[2]), "=r"(r[3]) : "r"(addr));
}

__device__ __forceinline__ void ldmatrix_x2t(uint32_t& b0, uint32_t& b1, uint32_t addr) {
    asm volatile("ldmatrix.sync.aligned.m8n8.x2.trans.shared.b16 {%0,%1}, [%2];"
                 : "=r"(b0), "=r"(b1) : "r"(addr));
}

__device__ __forceinline__ void mma_bf16(float d[4], const uint32_t a[4],
                                         uint32_t b0, uint32_t b1) {
    asm volatile(
        "mma.sync.aligned.m16n8k16.row.col.f32.bf16.bf16.f32 "
        "{%0,%1,%2,%3}, {%4,%5,%6,%7}, {%8,%9}, {%0,%1,%2,%3};"
        : "+f"(d[0]), "+f"(d[1]), "+f"(d[2]), "+f"(d[3])
        : "r"(a[0]), "r"(a[1]), "r"(a[2]), "r"(a[3]), "r"(b0), "r"(b1));
}

// ---------------------------------------------------------------------------
// CSR build: degree histogram -> scan -> fill
// ---------------------------------------------------------------------------
__global__ void k_deg(const int* __restrict__ ei, int E) {
    int e = blockIdx.x * blockDim.x + threadIdx.x;
    if (e < E) atomicAdd(&g_deg[ei[E + e]], 1);
}

__global__ void k_scan1(int N) {
    __shared__ int s[256];
    int idx = blockIdx.x * 256 + threadIdx.x;
    int v = (idx < N) ? g_deg[idx] : 0;
    s[threadIdx.x] = v;
    __syncthreads();
    for (int off = 128; off > 0; off >>= 1) {
        if (threadIdx.x < off) s[threadIdx.x] += s[threadIdx.x + off];
        __syncthreads();
    }
    if (threadIdx.x == 0) g_bsum[blockIdx.x] = s[0];
}

__global__ void k_scan2(int nb, int E) {
    if (threadIdx.x == 0) {
        int run = 0;
        for (int i = 0; i < nb; i++) { g_boff[i] = run; run += g_bsum[i]; }
        g_rowptr[NN] = E;
    }
}

__global__ void k_scan3(int N) {
    __shared__ int s[256];
    int t = threadIdx.x;
    int idx = blockIdx.x * 256 + t;
    int v = (idx < N) ? g_deg[idx] : 0;
    s[t] = v;
    __syncthreads();
#pragma unroll
    for (int off = 1; off < 256; off <<= 1) {
        int add = (t >= off) ? s[t - off] : 0;
        __syncthreads();
        s[t] += add;
        __syncthreads();
    }
    if (idx < N) {
        int ex = s[t] - v + g_boff[blockIdx.x];
        g_rowptr[idx] = ex;
        g_cursor[idx] = ex;
    }
}

__global__ void k_fill(const int* __restrict__ ei, int E) {
    int e = blockIdx.x * blockDim.x + threadIdx.x;
    if (e < E) {
        int s = ei[e];
        int d = ei[E + e];
        int pos = atomicAdd(&g_cursor[d], 1);
        g_csrc[pos] = s;
    }
}

// ---------------------------------------------------------------------------
// Scalar aggregation for layer 1 + inverse degree
// ---------------------------------------------------------------------------
__global__ void k_aggx(const float* __restrict__ x, int N) {
    int n = blockIdx.x * blockDim.x + threadIdx.x;
    if (n < N) {
        int beg = g_rowptr[n], end = g_rowptr[n + 1];
        float s = 0.0f;
        for (int i = beg; i < end; i++) s += __ldg(&x[g_csrc[i]]);
        g_aggx[n] = s;
        g_inv[n] = 1.0f / fmaxf((float)(end - beg), 1.0f);
    }
}

__global__ void k_gcnt(const int* __restrict__ batch, int N) {
    int t = blockIdx.x * blockDim.x + threadIdx.x;
    int n0 = t * 32;
    if (n0 >= N) return;
    int ne = min(n0 + 32, N);
    int cur = batch[n0];
    float c = 0.0f;
    for (int n = n0; n < ne; n++) {
        int b = batch[n];
        if (b != cur) { atomicAdd(&g_gcnt[cur], c); c = 0.0f; cur = b; }
        c += 1.0f;
    }
    atomicAdd(&g_gcnt[cur], c);
}

// ---------------------------------------------------------------------------
// Layer 1 (exact fp32, rank-2), half2 output
// ---------------------------------------------------------------------------
__global__ void k_layer1(const float* __restrict__ x,
                         const float* __restrict__ W1l,
                         const float* __restrict__ W1r,
                         const float* __restrict__ b1, int N) {
    int i = blockIdx.x * blockDim.x + threadIdx.x;
    if (i < N * (HID / 2)) {
        int n = i >> 6;
        int j = (i & 63) * 2;
        float mean = g_aggx[n] * g_inv[n];
        float xv = __ldg(&x[n]);
        float2 wl = *(const float2*)(W1l + j);
        float2 wr = *(const float2*)(W1r + j);
        float2 bb = *(const float2*)(b1 + j);
        float v0 = fmaxf(fmaf(mean, wl.x, fmaf(xv, wr.x, bb.x)), 0.0f);
        float v1 = fmaxf(fmaf(mean, wl.y, fmaf(xv, wr.y, bb.y)), 0.0f);
        ((__half2*)g_h1h)[i] = __floats2half2_rn(v0, v1);
    }
}

// ---------------------------------------------------------------------------
// CSR gather aggregation over fp16 rows: one warp per dst node.
// Lane reads uint2 (4 halves) -> accumulates float4 -> writes fp32 agg.
// ---------------------------------------------------------------------------
__global__ void k_gather(const __half* __restrict__ h, int N) {
    int gt = blockIdx.x * blockDim.x + threadIdx.x;
    int node = gt >> 5;
    int lane = gt & 31;
    if (node >= N) return;
    int beg = g_rowptr[node], end = g_rowptr[node + 1];
    float4 a = make_float4(0.f, 0.f, 0.f, 0.f);
    int i = beg;
    for (; i + 1 < end; i += 2) {
        int s0 = g_csrc[i], s1 = g_csrc[i + 1];
        uint2 u0 = __ldg((const uint2*)(h + (size_t)s0 * HID) + lane);
        uint2 u1 = __ldg((const uint2*)(h + (size_t)s1 * HID) + lane);
        float2 f0 = __half22float2(*(__half2*)&u0.x);
        float2 f1 = __half22float2(*(__half2*)&u0.y);
        float2 f2 = __half22float2(*(__half2*)&u1.x);
        float2 f3 = __half22float2(*(__half2*)&u1.y);
        a.x += f0.x + f2.x; a.y += f0.y + f2.y;
        a.z += f1.x + f3.x; a.w += f1.y + f3.y;
    }
    if (i < end) {
        int s0 = g_csrc[i];
        uint2 u0 = __ldg((const uint2*)(h + (size_t)s0 * HID) + lane);
        float2 f0 = __half22float2(*(__half2*)&u0.x);
        float2 f1 = __half22float2(*(__half2*)&u0.y);
        a.x += f0.x; a.y += f0.y; a.z += f1.x; a.w += f1.y;
    }
    g_aggv[(size_t)node * 32 + lane] = a;
}

// ---------------------------------------------------------------------------
// Weight prep: B chunk images [64 k][136 n(pad)] bf16 per chunk.
// chunks 0-3 = Bh (K 0..255), 4-7 = Bl. W'[k][n]: k<128 -> Wl, else Wr.
// ---------------------------------------------------------------------------
__global__ void k_prepB(const float* __restrict__ Wl,
                        const float* __restrict__ Wr, int layer) {
    int t = blockIdx.x * blockDim.x + threadIdx.x;
    if (t >= 8 * 64 * 64) return;
    int ci = t >> 12;
    int rem = t & 4095;
    int k = rem >> 6;
    int np = rem & 63;
    int n = np * 2;
    int kk = (ci & 3) * 64 + k;
    float w0 = (kk < 128) ? Wl[kk * HID + n] : Wr[(kk - 128) * HID + n];
    float w1 = (kk < 128) ? Wl[kk * HID + n + 1] : Wr[(kk - 128) * HID + n + 1];
    __nv_bfloat16 b0, b1;
    if (ci < 4) {
        b0 = __float2bfloat16(w0);
        b1 = __float2bfloat16(w1);
    } else {
        __nv_bfloat16 h0 = __float2bfloat16(w0), h1 = __float2bfloat16(w1);
        b0 = __float2bfloat16(w0 - __bfloat162float(h0));
        b1 = __float2bfloat16(w1 - __bfloat162float(h1));
    }
    g_Bp[layer * 34816 + ci * 4352 + k * 68 + np] = pack_bf16x2(b0, b1);
}

// ---------------------------------------------------------------------------
// Fused SAGE GEMM via mma.sync bf16, 3M split (K_eff = 768):
//   hout = relu( [agg*inv | hin] @ [Wl;Wr] + b )  -> fp16 out
// 128x128 tile / block, 256 threads. cp.async double-buffered B chunks
// (8 loads, 12 compute passes: Bh reused for Ah & Al terms).
// ---------------------------------------------------------------------------
#define AP 528          // A row stride bytes (264 bf16, odd 16B-stride)
#define BP 272          // B row stride bytes (136 bf16)
#define SM_AL 67584
#define SM_B  135168
#define BCH   17408
#define SMEM_GEMM (135168 + 2 * 17408)

__device__ __forceinline__ void prefB(char* smdst, const uint32_t* src, int tid) {
    uint32_t d = smem_u32(smdst);
#pragma unroll
    for (int m = 0; m < 5; m++) {
        int i = tid + m * 256;
        if (i < 1088)
            asm volatile("cp.async.cg.shared.global [%0], [%1], 16;"
                         :: "r"(d + i * 16), "l"((const uint4*)src + i) : "memory");
    }
    asm volatile("cp.async.commit_group;" ::: "memory");
}

__global__ __launch_bounds__(256, 1)
void k_gemm(const __half* __restrict__ hin, __half* __restrict__ hout,
            const float* __restrict__ bias, int layer, int N) {
    extern __shared__ char sm[];
    uint32_t smb = smem_u32(sm);
    int tid = threadIdx.x;
    int lane = tid & 31;
    int wid = tid >> 5;
    int n0 = blockIdx.x * 128;
    const float* aggf = (const float*)g_aggv;
    const uint32_t* Bpl = g_Bp + layer * 34816;

    // Kick off first two B-chunk prefetches; they overlap the A-split stage.
    prefB(sm + SM_B, Bpl, tid);
    prefB(sm + SM_B + BCH, Bpl + 4352, tid);

    // --- Stage A: inputs -> (Ah, Al) bf16 split tiles in smem ---
#pragma unroll 4
    for (int it = 0; it < 64; it++) {
        int idx = tid + it * 256;
        int r = idx >> 7;
        int p = idx & 127;
        int node = n0 + r;
        float2 v = make_float2(0.f, 0.f);
        if (node < N) {
            if (p < 64) {
                v = ((const float2*)(aggf + (size_t)node * HID))[p];
                float s = g_inv[node];
                v.x *= s; v.y *= s;
            } else {
                v = __half22float2(((const __half2*)(hin + (size_t)node * HID))[p - 64]);
            }
        }
        __nv_bfloat16 hx = __float2bfloat16(v.x), hy = __float2bfloat16(v.y);
        __nv_bfloat16 gx = __float2bfloat16(v.x - __bfloat162float(hx));
        __nv_bfloat16 gy = __float2bfloat16(v.y - __bfloat162float(hy));
        *(uint32_t*)(sm + r * AP + p * 4) = pack_bf16x2(hx, hy);
        *(uint32_t*)(sm + SM_AL + r * AP + p * 4) = pack_bf16x2(gx, gy);
    }

    float acc[2][8][4];
#pragma unroll
    for (int s = 0; s < 2; s++)
#pragma unroll
        for (int nt = 0; nt < 8; nt++)
#pragma unroll
            for (int q = 0; q < 4; q++) acc[s][nt][q] = 0.0f;

    int wr = wid & 3;
    int wc = wid >> 2;
    int a_r = lane & 15;
    int a_c8 = (lane >> 4) << 3;
    int b_r = lane & 15;

    for (int ci = 0; ci < 8; ci++) {
        if (ci >= 1 && ci < 7)
            prefB(sm + SM_B + ((ci + 1) & 1) * BCH, Bpl + (ci + 1) * 4352, tid);
        if (ci < 7) asm volatile("cp.async.wait_group 1;" ::: "memory");
        else        asm volatile("cp.async.wait_group 0;" ::: "memory");
        __syncthreads();

        int kc = ci & 3;
        int acol0 = kc * 64;
        int nterms = (ci < 4) ? 2 : 1;
        uint32_t bbuf = smb + SM_B + (uint32_t)(ci & 1) * BCH;

        for (int t = 0; t < nterms; t++) {
            uint32_t abase = smb + ((t == 1) ? SM_AL : 0);
#pragma unroll
            for (int ks = 0; ks < 4; ks++) {
                int k0 = acol0 + ks * 16;
                uint32_t a0[4], a1[4];
                uint32_t addr0 = abase + (uint32_t)((wr * 32 + a_r) * AP + (k0 + a_c8) * 2);
                ldmatrix_x4(a0, addr0);
                ldmatrix_x4(a1, addr0 + 16 * AP);
                uint32_t bbase = bbuf + (uint32_t)((ks * 16 + b_r) * BP + wc * 128);
#pragma unroll
                for (int nt = 0; nt < 8; nt++) {
                    uint32_t b0, b1;
                    ldmatrix_x2t(b0, b1, bbase + nt * 16);
                    mma_bf16(acc[0][nt], a0, b0, b1);
                    mma_bf16(acc[1][nt], a1, b0, b1);
                }
            }
        }
        __syncthreads();
    }

    // --- Epilogue: bias + relu -> fp16 ---
    int qr = lane >> 2;
    int qc = (lane & 3) * 2;
#pragma unroll
    for (int s = 0; s < 2; s++) {
        int mb = n0 + wr * 32 + s * 16;
#pragma unroll
        for (int nt = 0; nt < 8; nt++) {
            int col = wc * 64 + nt * 8 + qc;
            float2 bv = *(const float2*)(bias + col);
            int mlo = mb + qr;
            int mhi = mlo + 8;
            if (mlo < N) {
                float o0 = fmaxf(acc[s][nt][0] + bv.x, 0.f);
                float o1 = fmaxf(acc[s][nt][1] + bv.y, 0.f);
                *(__half2*)(hout + (size_t)mlo * HID + col) = __floats2half2_rn(o0, o1);
            }
            if (mhi < N) {
                float o0 = fmaxf(acc[s][nt][2] + bv.x, 0.f);
                float o1 = fmaxf(acc[s][nt][3] + bv.y, 0.f);
                *(__half2*)(hout + (size_t)mhi * HID + col) = __floats2half2_rn(o0, o1);
            }
        }
    }
}

// ---------------------------------------------------------------------------
// Mean pool: run-length compressed atomics (batch sorted), fp16 input
// ---------------------------------------------------------------------------
__global__ void k_pool(const __half* __restrict__ h,
                       const int* __restrict__ batch, int N) {
    int j = threadIdx.x;
    int n0 = blockIdx.x * 64;
    if (n0 >= N) return;
    int ne = min(n0 + 64, N);
    int cur = batch[n0];
    float acc = 0.0f;
    for (int n = n0; n < ne; n++) {
        int b = batch[n];
        if (b != cur) {
            atomicAdd(&g_pool[cur * HID + j], acc);
            acc = 0.0f;
            cur = b;
        }
        acc += __half2float(h[(size_t)n * HID + j]);
    }
    atomicAdd(&g_pool[cur * HID + j], acc);
}

// ---------------------------------------------------------------------------
// Head: logits = (pool/gcnt) @ Wfc + bfc ; log_softmax
// ---------------------------------------------------------------------------
__global__ void k_head(const float* __restrict__ Wfc,
                       const float* __restrict__ bfc,
                       float* __restrict__ out) {
    __shared__ float lg[NG][NC];
    int t = threadIdx.x;
    if (t < NG * NC) {
        int g = t / NC;
        int c = t % NC;
        float ginv = 1.0f / fmaxf(g_gcnt[g], 1.0f);
        float s = __ldg(&bfc[c]);
        for (int k = 0; k < HID; k++)
            s = fmaf(g_pool[g * HID + k] * ginv, __ldg(&Wfc[k * NC + c]), s);
        lg[g][c] = s;
    }
    __syncthreads();
    if (t < NG) {
        float m = -1e30f;
        for (int c = 0; c < NC; c++) m = fmaxf(m, lg[t][c]);
        float se = 0.0f;
        for (int c = 0; c < NC; c++) se += expf(lg[t][c] - m);
        float lse = m + logf(se);
        for (int c = 0; c < NC; c++) out[t * NC + c] = lg[t][c] - lse;
    }
}

// ---------------------------------------------------------------------------
extern "C" void kernel_launch(void* const* d_in, const int* in_sizes, int n_in,
                              void* d_out, int out_size) {
    const float* x   = (const float*)d_in[0];
    const int* ei    = (const int*)d_in[1];
    const int* batch = (const int*)d_in[2];
    const float* W1l = (const float*)d_in[3];
    const float* W1r = (const float*)d_in[4];
    const float* b1  = (const float*)d_in[5];
    const float* W2l = (const float*)d_in[6];
    const float* W2r = (const float*)d_in[7];
    const float* b2  = (const float*)d_in[8];
    const float* W3l = (const float*)d_in[9];
    const float* W3r = (const float*)d_in[10];
    const float* b3  = (const float*)d_in[11];
    const float* Wfc = (const float*)d_in[12];
    const float* bfc = (const float*)d_in[13];
    float* out = (float*)d_out;

    int N = in_sizes[0];
    int E = in_sizes[1] / 2;
    int nb = (N + 255) / 256;

    void *p_deg, *p_gcnt, *p_pool, *p_h1, *p_h2;
    cudaGetSymbolAddress(&p_deg, g_deg);
    cudaGetSymbolAddress(&p_gcnt, g_gcnt);
    cudaGetSymbolAddress(&p_pool, g_pool);
    cudaGetSymbolAddress(&p_h1, g_h1h);
    cudaGetSymbolAddress(&p_h2, g_h2h);

    cudaFuncSetAttribute(k_gemm, cudaFuncAttributeMaxDynamicSharedMemorySize, SMEM_GEMM);

    cudaMemsetAsync(p_deg, 0, (size_t)N * 4);
    cudaMemsetAsync(p_gcnt, 0, NG * 4);
    cudaMemsetAsync(p_pool, 0, NG * HID * 4);

    // CSR build
    k_deg<<<(E + 255) / 256, 256>>>(ei, E);
    k_scan1<<<nb, 256>>>(N);
    k_scan2<<<1, 32>>>(nb, E);
    k_scan3<<<nb, 256>>>(N);
    k_fill<<<(E + 255) / 256, 256>>>(ei, E);

    // Prep + layer 1
    k_aggx<<<(N + 255) / 256, 256>>>(x, N);
    k_gcnt<<<((N + 31) / 32 + 255) / 256, 256>>>(batch, N);
    k_prepB<<<128, 256>>>(W2l, W2r, 0);
    k_prepB<<<128, 256>>>(W3l, W3r, 1);
    k_layer1<<<(N * (HID / 2) + 255) / 256, 256>>>(x, W1l, W1r, b1, N);

    int gat_blocks = (N * 32 + 255) / 256;
    int gemm_blocks = (N + 127) / 128;

    // Layer 2
    k_gather<<<gat_blocks, 256>>>((const __half*)p_h1, N);
    k_gemm<<<gemm_blocks, 256, SMEM_GEMM>>>((const __half*)p_h1, (__half*)p_h2, b2, 0, N);

    // Layer 3
    k_gather<<<gat_blocks, 256>>>((const __half*)p_h2, N);
    k_gemm<<<gemm_blocks, 256, SMEM_GEMM>>>((const __half*)p_h2, (__half*)p_h1, b3, 1, N);

    // Pool + head
    k_pool<<<(N + 63) / 64, 128>>>((const __half*)p_h1, batch, N);
    k_head<<<1, 640>>>(Wfc, bfc, out);
}

// round 7
// speedup vs baseline: 2.6505x; 1.5540x over previous
#include <cuda_runtime.h>
#include <cuda_bf16.h>
#include <cuda_fp16.h>
#include <cstdint>

#define NN 100000
#define NE 1600000
#define HID 128
#define NG 64
#define NC 10

// ---------------------------------------------------------------------------
// Persistent scratch (static __device__ arrays — no runtime allocation).
// ---------------------------------------------------------------------------
__device__ __half g_h1h[NN * HID];     // fp16 activations (ping)
__device__ __half g_h2h[NN * HID];     // fp16 activations (pong)
__device__ __half g_aggh[NN * HID];    // fp16 neighbor-sum buffer
__device__ float g_inv[NN];
__device__ float g_aggx[NN];
__device__ float g_pool[NG * HID];
__device__ float g_gcnt[NG];
// CSR
__device__ int g_deg[NN];
__device__ int g_rowptr[NN + 1];
__device__ int g_cursor[NN];
__device__ int g_csrc[NE];
__device__ int g_bsum[512];
__device__ int g_boff[512];
// Pre-split B chunk images: 2 layers x 8 chunks x [64 k][136 n(pad)] bf16
__device__ uint32_t g_Bp[2 * 8 * 4352];

// ---------------------------------------------------------------------------
// Helpers
// ---------------------------------------------------------------------------
__device__ __forceinline__ uint32_t smem_u32(const void* p) {
    uint32_t a;
    asm("{ .reg .u64 t; cvta.to.shared.u64 t, %1; cvt.u32.u64 %0, t; }"
        : "=r"(a) : "l"(p));
    return a;
}

__device__ __forceinline__ uint32_t pack_bf16x2(__nv_bfloat16 lo, __nv_bfloat16 hi) {
    return ((uint32_t)__bfloat16_as_ushort(hi) << 16) | __bfloat16_as_ushort(lo);
}

__device__ __forceinline__ void ldmatrix_x4(uint32_t r[4], uint32_t addr) {
    asm volatile("ldmatrix.sync.aligned.m8n8.x4.shared.b16 {%0,%1,%2,%3}, [%4];"
                 : "=r"(r[0]), "=r"(r[1]), "=r"(r[2]), "=r"(r[3]) : "r"(addr));
}

__device__ __forceinline__ void ldmatrix_x2t(uint32_t& b0, uint32_t& b1, uint32_t addr) {
    asm volatile("ldmatrix.sync.aligned.m8n8.x2.trans.shared.b16 {%0,%1}, [%2];"
                 : "=r"(b0), "=r"(b1) : "r"(addr));
}

__device__ __forceinline__ void mma_bf16(float d[4], const uint32_t a[4],
                                         uint32_t b0, uint32_t b1) {
    asm volatile(
        "mma.sync.aligned.m16n8k16.row.col.f32.bf16.bf16.f32 "
        "{%0,%1,%2,%3}, {%4,%5,%6,%7}, {%8,%9}, {%0,%1,%2,%3};"
        : "+f"(d[0]), "+f"(d[1]), "+f"(d[2]), "+f"(d[3])
        : "r"(a[0]), "r"(a[1]), "r"(a[2]), "r"(a[3]), "r"(b0), "r"(b1));
}

// ---------------------------------------------------------------------------
// CSR build: degree histogram -> scan -> fill
// ---------------------------------------------------------------------------
__global__ void k_deg(const int* __restrict__ ei, int E) {
    int e = blockIdx.x * blockDim.x + threadIdx.x;
    if (e < E) atomicAdd(&g_deg[ei[E + e]], 1);
}

__global__ void k_scan1(int N) {
    __shared__ int s[256];
    int idx = blockIdx.x * 256 + threadIdx.x;
    int v = (idx < N) ? g_deg[idx] : 0;
    s[threadIdx.x] = v;
    __syncthreads();
    for (int off = 128; off > 0; off >>= 1) {
        if (threadIdx.x < off) s[threadIdx.x] += s[threadIdx.x + off];
        __syncthreads();
    }
    if (threadIdx.x == 0) g_bsum[blockIdx.x] = s[0];
}

__global__ void k_scan2(int nb, int E) {
    int lane = threadIdx.x;  // one warp
    int run = 0;
    for (int base = 0; base < nb; base += 32) {
        int i = base + lane;
        int orig = (i < nb) ? g_bsum[i] : 0;
        int v = orig;
#pragma unroll
        for (int off = 1; off < 32; off <<= 1) {
            int t = __shfl_up_sync(0xffffffff, v, off);
            if (lane >= off) v += t;
        }
        if (i < nb) g_boff[i] = run + v - orig;
        run += __shfl_sync(0xffffffff, v, 31);
    }
    if (lane == 0) g_rowptr[NN] = E;
}

__global__ void k_scan3(int N) {
    __shared__ int s[256];
    int t = threadIdx.x;
    int idx = blockIdx.x * 256 + t;
    int v = (idx < N) ? g_deg[idx] : 0;
    s[t] = v;
    __syncthreads();
#pragma unroll
    for (int off = 1; off < 256; off <<= 1) {
        int add = (t >= off) ? s[t - off] : 0;
        __syncthreads();
        s[t] += add;
        __syncthreads();
    }
    if (idx < N) {
        int ex = s[t] - v + g_boff[blockIdx.x];
        g_rowptr[idx] = ex;
        g_cursor[idx] = ex;
    }
}

__global__ void k_fill(const int* __restrict__ ei, int E) {
    int e = blockIdx.x * blockDim.x + threadIdx.x;
    if (e < E) {
        int s = ei[e];
        int d = ei[E + e];
        int pos = atomicAdd(&g_cursor[d], 1);
        g_csrc[pos] = s;
    }
}

// ---------------------------------------------------------------------------
// Scalar aggregation for layer 1 + inverse degree
// ---------------------------------------------------------------------------
__global__ void k_aggx(const float* __restrict__ x, int N) {
    int n = blockIdx.x * blockDim.x + threadIdx.x;
    if (n < N) {
        int beg = g_rowptr[n], end = g_rowptr[n + 1];
        float s = 0.0f;
        for (int i = beg; i < end; i++) s += __ldg(&x[g_csrc[i]]);
        g_aggx[n] = s;
        g_inv[n] = 1.0f / fmaxf((float)(end - beg), 1.0f);
    }
}

__global__ void k_gcnt(const int* __restrict__ batch, int N) {
    int t = blockIdx.x * blockDim.x + threadIdx.x;
    int n0 = t * 32;
    if (n0 >= N) return;
    int ne = min(n0 + 32, N);
    int cur = batch[n0];
    float c = 0.0f;
    for (int n = n0; n < ne; n++) {
        int b = batch[n];
        if (b != cur) { atomicAdd(&g_gcnt[cur], c); c = 0.0f; cur = b; }
        c += 1.0f;
    }
    atomicAdd(&g_gcnt[cur], c);
}

// ---------------------------------------------------------------------------
// Layer 1 (exact fp32, rank-2), half2 output
// ---------------------------------------------------------------------------
__global__ void k_layer1(const float* __restrict__ x,
                         const float* __restrict__ W1l,
                         const float* __restrict__ W1r,
                         const float* __restrict__ b1, int N) {
    int i = blockIdx.x * blockDim.x + threadIdx.x;
    if (i < N * (HID / 2)) {
        int n = i >> 6;
        int j = (i & 63) * 2;
        float mean = g_aggx[n] * g_inv[n];
        float xv = __ldg(&x[n]);
        float2 wl = *(const float2*)(W1l + j);
        float2 wr = *(const float2*)(W1r + j);
        float2 bb = *(const float2*)(b1 + j);
        float v0 = fmaxf(fmaf(mean, wl.x, fmaf(xv, wr.x, bb.x)), 0.0f);
        float v1 = fmaxf(fmaf(mean, wl.y, fmaf(xv, wr.y, bb.y)), 0.0f);
        ((__half2*)g_h1h)[i] = __floats2half2_rn(v0, v1);
    }
}

// ---------------------------------------------------------------------------
// CSR gather aggregation: 2 nodes/warp, 16 lanes/node, uint4 (8-half) loads.
// Accumulate fp32, store fp16 sums.
// ---------------------------------------------------------------------------
__global__ void k_gather(const __half* __restrict__ h, int N) {
    int gt = blockIdx.x * blockDim.x + threadIdx.x;
    int node = gt >> 4;        // half-warp per node
    int lane = gt & 15;        // 16 B per lane covers the 256 B row
    if (node >= N) return;
    int beg = g_rowptr[node], end = g_rowptr[node + 1];
    float a0 = 0.f, a1 = 0.f, a2 = 0.f, a3 = 0.f;
    float a4 = 0.f, a5 = 0.f, a6 = 0.f, a7 = 0.f;
    int i = beg;
    for (; i + 1 < end; i += 2) {
        int s0 = g_csrc[i], s1 = g_csrc[i + 1];
        uint4 u0 = __ldg((const uint4*)(h + (size_t)s0 * HID) + lane);
        uint4 u1 = __ldg((const uint4*)(h + (size_t)s1 * HID) + lane);
        float2 p;
        p = __half22float2(*(__half2*)&u0.x); a0 += p.x; a1 += p.y;
        p = __half22float2(*(__half2*)&u0.y); a2 += p.x; a3 += p.y;
        p = __half22float2(*(__half2*)&u0.z); a4 += p.x; a5 += p.y;
        p = __half22float2(*(__half2*)&u0.w); a6 += p.x; a7 += p.y;
        p = __half22float2(*(__half2*)&u1.x); a0 += p.x; a1 += p.y;
        p = __half22float2(*(__half2*)&u1.y); a2 += p.x; a3 += p.y;
        p = __half22float2(*(__half2*)&u1.z); a4 += p.x; a5 += p.y;
        p = __half22float2(*(__half2*)&u1.w); a6 += p.x; a7 += p.y;
    }
    if (i < end) {
        int s0 = g_csrc[i];
        uint4 u0 = __ldg((const uint4*)(h + (size_t)s0 * HID) + lane);
        float2 p;
        p = __half22float2(*(__half2*)&u0.x); a0 += p.x; a1 += p.y;
        p = __half22float2(*(__half2*)&u0.y); a2 += p.x; a3 += p.y;
        p = __half22float2(*(__half2*)&u0.z); a4 += p.x; a5 += p.y;
        p = __half22float2(*(__half2*)&u0.w); a6 += p.x; a7 += p.y;
    }
    uint4 o;
    *(__half2*)&o.x = __floats2half2_rn(a0, a1);
    *(__half2*)&o.y = __floats2half2_rn(a2, a3);
    *(__half2*)&o.z = __floats2half2_rn(a4, a5);
    *(__half2*)&o.w = __floats2half2_rn(a6, a7);
    ((uint4*)(g_aggh + (size_t)node * HID))[lane] = o;
}

// ---------------------------------------------------------------------------
// Weight prep: B chunk images [64 k][136 n(pad)] bf16 per chunk.
// chunks 0-3 = Bh (K 0..255), 4-7 = Bl. W'[k][n]: k<128 -> Wl, else Wr.
// ---------------------------------------------------------------------------
__global__ void k_prepB(const float* __restrict__ Wl,
                        const float* __restrict__ Wr, int layer) {
    int t = blockIdx.x * blockDim.x + threadIdx.x;
    if (t >= 8 * 64 * 64) return;
    int ci = t >> 12;
    int rem = t & 4095;
    int k = rem >> 6;
    int np = rem & 63;
    int n = np * 2;
    int kk = (ci & 3) * 64 + k;
    float w0 = (kk < 128) ? Wl[kk * HID + n] : Wr[(kk - 128) * HID + n];
    float w1 = (kk < 128) ? Wl[kk * HID + n + 1] : Wr[(kk - 128) * HID + n + 1];
    __nv_bfloat16 b0, b1;
    if (ci < 4) {
        b0 = __float2bfloat16(w0);
        b1 = __float2bfloat16(w1);
    } else {
        __nv_bfloat16 h0 = __float2bfloat16(w0), h1 = __float2bfloat16(w1);
        b0 = __float2bfloat16(w0 - __bfloat162float(h0));
        b1 = __float2bfloat16(w1 - __bfloat162float(h1));
    }
    g_Bp[layer * 34816 + ci * 4352 + k * 68 + np] = pack_bf16x2(b0, b1);
}

// ---------------------------------------------------------------------------
// Fused SAGE GEMM via mma.sync bf16, 3M split (K_eff = 768):
//   hout = relu( [agg*inv | hin] @ [Wl;Wr] + b )  -> fp16 out
// 64x128 tile / block (occ=2), 256 threads, cp.async double-buffered B.
// smem: Ah[64][264] (33792B) | Al (33792B) | B dbuf (2x17408B) = 102400B
// ---------------------------------------------------------------------------
#define AP 528          // A row stride bytes (264 bf16, odd 16B-stride)
#define BP 272          // B row stride bytes (136 bf16)
#define SM_AL 33792
#define SM_B  67584
#define BCH   17408
#define SMEM_GEMM (67584 + 2 * 17408)

__device__ __forceinline__ void prefB(char* smdst, const uint32_t* src, int tid) {
    uint32_t d = smem_u32(smdst);
#pragma unroll
    for (int m = 0; m < 5; m++) {
        int i = tid + m * 256;
        if (i < 1088)
            asm volatile("cp.async.cg.shared.global [%0], [%1], 16;"
                         :: "r"(d + i * 16), "l"((const uint4*)src + i) : "memory");
    }
    asm volatile("cp.async.commit_group;" ::: "memory");
}

__global__ __launch_bounds__(256)
void k_gemm(const __half* __restrict__ hin, __half* __restrict__ hout,
            const float* __restrict__ bias, int layer, int N) {
    extern __shared__ char sm[];
    uint32_t smb = smem_u32(sm);
    int tid = threadIdx.x;
    int lane = tid & 31;
    int wid = tid >> 5;
    int n0 = blockIdx.x * 64;
    const uint32_t* Bpl = g_Bp + layer * 34816;

    // Kick off first two B-chunk prefetches; they overlap the A-split stage.
    prefB(sm + SM_B, Bpl, tid);
    prefB(sm + SM_B + BCH, Bpl + 4352, tid);

    // --- Stage A: inputs -> (Ah, Al) bf16 split tiles in smem (64 rows) ---
#pragma unroll 4
    for (int it = 0; it < 32; it++) {
        int idx = tid + it * 256;
        int r = idx >> 7;          // 0..63
        int p = idx & 127;
        int node = n0 + r;
        float2 v = make_float2(0.f, 0.f);
        if (node < N) {
            if (p < 64) {
                v = __half22float2(((const __half2*)(g_aggh + (size_t)node * HID))[p]);
                float s = g_inv[node];
                v.x *= s; v.y *= s;
            } else {
                v = __half22float2(((const __half2*)(hin + (size_t)node * HID))[p - 64]);
            }
        }
        __nv_bfloat16 hx = __float2bfloat16(v.x), hy = __float2bfloat16(v.y);
        __nv_bfloat16 gx = __float2bfloat16(v.x - __bfloat162float(hx));
        __nv_bfloat16 gy = __float2bfloat16(v.y - __bfloat162float(hy));
        *(uint32_t*)(sm + r * AP + p * 4) = pack_bf16x2(hx, hy);
        *(uint32_t*)(sm + SM_AL + r * AP + p * 4) = pack_bf16x2(gx, gy);
    }

    float acc[2][4][4];
#pragma unroll
    for (int s = 0; s < 2; s++)
#pragma unroll
        for (int nt = 0; nt < 4; nt++)
#pragma unroll
            for (int q = 0; q < 4; q++) acc[s][nt][q] = 0.0f;

    int wr = wid & 1;          // 2 row groups of 32
    int wc = wid >> 1;         // 4 col groups of 32
    int a_r = lane & 15;
    int a_c8 = (lane >> 4) << 3;
    int b_r = lane & 15;

    for (int ci = 0; ci < 8; ci++) {
        if (ci >= 1 && ci < 7)
            prefB(sm + SM_B + ((ci + 1) & 1) * BCH, Bpl + (ci + 1) * 4352, tid);
        if (ci < 7) asm volatile("cp.async.wait_group 1;" ::: "memory");
        else        asm volatile("cp.async.wait_group 0;" ::: "memory");
        __syncthreads();

        int kc = ci & 3;
        int acol0 = kc * 64;
        int nterms = (ci < 4) ? 2 : 1;
        uint32_t bbuf = smb + SM_B + (uint32_t)(ci & 1) * BCH;

        for (int t = 0; t < nterms; t++) {
            uint32_t abase = smb + ((t == 1) ? SM_AL : 0);
#pragma unroll
            for (int ks = 0; ks < 4; ks++) {
                int k0 = acol0 + ks * 16;
                uint32_t a0[4], a1[4];
                uint32_t addr0 = abase + (uint32_t)((wr * 32 + a_r) * AP + (k0 + a_c8) * 2);
                ldmatrix_x4(a0, addr0);
                ldmatrix_x4(a1, addr0 + 16 * AP);
                uint32_t bbase = bbuf + (uint32_t)((ks * 16 + b_r) * BP + wc * 64);
#pragma unroll
                for (int nt = 0; nt < 4; nt++) {
                    uint32_t b0, b1;
                    ldmatrix_x2t(b0, b1, bbase + nt * 16);
                    mma_bf16(acc[0][nt], a0, b0, b1);
                    mma_bf16(acc[1][nt], a1, b0, b1);
                }
            }
        }
        __syncthreads();
    }

    // --- Epilogue: bias + relu -> fp16 ---
    int qr = lane >> 2;
    int qc = (lane & 3) * 2;
#pragma unroll
    for (int s = 0; s < 2; s++) {
        int mb = n0 + wr * 32 + s * 16;
#pragma unroll
        for (int nt = 0; nt < 4; nt++) {
            int col = wc * 32 + nt * 8 + qc;
            float2 bv = *(const float2*)(bias + col);
            int mlo = mb + qr;
            int mhi = mlo + 8;
            if (mlo < N) {
                float o0 = fmaxf(acc[s][nt][0] + bv.x, 0.f);
                float o1 = fmaxf(acc[s][nt][1] + bv.y, 0.f);
                *(__half2*)(hout + (size_t)mlo * HID + col) = __floats2half2_rn(o0, o1);
            }
            if (mhi < N) {
                float o0 = fmaxf(acc[s][nt][2] + bv.x, 0.f);
                float o1 = fmaxf(acc[s][nt][3] + bv.y, 0.f);
                *(__half2*)(hout + (size_t)mhi * HID + col) = __floats2half2_rn(o0, o1);
            }
        }
    }
}

// ---------------------------------------------------------------------------
// Mean pool: run-length compressed atomics (batch sorted), fp16 input
// ---------------------------------------------------------------------------
__global__ void k_pool(const __half* __restrict__ h,
                       const int* __restrict__ batch, int N) {
    int j = threadIdx.x;
    int n0 = blockIdx.x * 64;
    if (n0 >= N) return;
    int ne = min(n0 + 64, N);
    int cur = batch[n0];
    float acc = 0.0f;
    for (int n = n0; n < ne; n++) {
        int b = batch[n];
        if (b != cur) {
            atomicAdd(&g_pool[cur * HID + j], acc);
            acc = 0.0f;
            cur = b;
        }
        acc += __half2float(h[(size_t)n * HID + j]);
    }
    atomicAdd(&g_pool[cur * HID + j], acc);
}

// ---------------------------------------------------------------------------
// Head: logits = (pool/gcnt) @ Wfc + bfc ; log_softmax
// ---------------------------------------------------------------------------
__global__ void k_head(const float* __restrict__ Wfc,
                       const float* __restrict__ bfc,
                       float* __restrict__ out) {
    __shared__ float lg[NG][NC];
    int t = threadIdx.x;
    if (t < NG * NC) {
        int g = t / NC;
        int c = t % NC;
        float ginv = 1.0f / fmaxf(g_gcnt[g], 1.0f);
        float s = __ldg(&bfc[c]);
        for (int k = 0; k < HID; k++)
            s = fmaf(g_pool[g * HID + k] * ginv, __ldg(&Wfc[k * NC + c]), s);
        lg[g][c] = s;
    }
    __syncthreads();
    if (t < NG) {
        float m = -1e30f;
        for (int c = 0; c < NC; c++) m = fmaxf(m, lg[t][c]);
        float se = 0.0f;
        for (int c = 0; c < NC; c++) se += expf(lg[t][c] - m);
        float lse = m + logf(se);
        for (int c = 0; c < NC; c++) out[t * NC + c] = lg[t][c] - lse;
    }
}

// ---------------------------------------------------------------------------
extern "C" void kernel_launch(void* const* d_in, const int* in_sizes, int n_in,
                              void* d_out, int out_size) {
    const float* x   = (const float*)d_in[0];
    const int* ei    = (const int*)d_in[1];
    const int* batch = (const int*)d_in[2];
    const float* W1l = (const float*)d_in[3];
    const float* W1r = (const float*)d_in[4];
    const float* b1  = (const float*)d_in[5];
    const float* W2l = (const float*)d_in[6];
    const float* W2r = (const float*)d_in[7];
    const float* b2  = (const float*)d_in[8];
    const float* W3l = (const float*)d_in[9];
    const float* W3r = (const float*)d_in[10];
    const float* b3  = (const float*)d_in[11];
    const float* Wfc = (const float*)d_in[12];
    const float* bfc = (const float*)d_in[13];
    float* out = (float*)d_out;

    int N = in_sizes[0];
    int E = in_sizes[1] / 2;
    int nb = (N + 255) / 256;

    void *p_deg, *p_gcnt, *p_pool, *p_h1, *p_h2;
    cudaGetSymbolAddress(&p_deg, g_deg);
    cudaGetSymbolAddress(&p_gcnt, g_gcnt);
    cudaGetSymbolAddress(&p_pool, g_pool);
    cudaGetSymbolAddress(&p_h1, g_h1h);
    cudaGetSymbolAddress(&p_h2, g_h2h);

    cudaFuncSetAttribute(k_gemm, cudaFuncAttributeMaxDynamicSharedMemorySize, SMEM_GEMM);

    cudaMemsetAsync(p_deg, 0, (size_t)N * 4);
    cudaMemsetAsync(p_gcnt, 0, NG * 4);
    cudaMemsetAsync(p_pool, 0, NG * HID * 4);

    // CSR build
    k_deg<<<(E + 255) / 256, 256>>>(ei, E);
    k_scan1<<<nb, 256>>>(N);
    k_scan2<<<1, 32>>>(nb, E);
    k_scan3<<<nb, 256>>>(N);
    k_fill<<<(E + 255) / 256, 256>>>(ei, E);

    // Prep + layer 1
    k_aggx<<<(N + 255) / 256, 256>>>(x, N);
    k_gcnt<<<((N + 31) / 32 + 255) / 256, 256>>>(batch, N);
    k_prepB<<<128, 256>>>(W2l, W2r, 0);
    k_prepB<<<128, 256>>>(W3l, W3r, 1);
    k_layer1<<<(N * (HID / 2) + 255) / 256, 256>>>(x, W1l, W1r, b1, N);

    int gat_blocks = (N * 16 + 255) / 256;
    int gemm_blocks = (N + 63) / 64;

    // Layer 2
    k_gather<<<gat_blocks, 256>>>((const __half*)p_h1, N);
    k_gemm<<<gemm_blocks, 256, SMEM_GEMM>>>((const __half*)p_h1, (__half*)p_h2, b2, 0, N);

    // Layer 3
    k_gather<<<gat_blocks, 256>>>((const __half*)p_h2, N);
    k_gemm<<<gemm_blocks, 256, SMEM_GEMM>>>((const __half*)p_h2, (__half*)p_h1, b3, 1, N);

    // Pool + head
    k_pool<<<(N + 63) / 64, 128>>>((const __half*)p_h1, batch, N);
    k_head<<<1, 640>>>(Wfc, bfc, out);
}

// round 9
// speedup vs baseline: 3.8302x; 1.4451x over previous
#include <cuda_runtime.h>
#include <cuda_fp16.h>
#include <cstdint>

#define NN 100000
#define NE 1600000
#define HID 128
#define NG 64
#define NC 10

// ---------------------------------------------------------------------------
// Persistent scratch (static __device__ arrays — no runtime allocation).
// ---------------------------------------------------------------------------
__device__ __half g_h1h[NN * HID];     // fp16 activations (ping)
__device__ __half g_h2h[NN * HID];     // fp16 activations (pong)
__device__ __half g_meanh[NN * HID];   // fp16 neighbor-mean buffer
__device__ float g_inv[NN];
__device__ float g_aggx[NN];
__device__ float g_pool[NG * HID];
__device__ float g_gcnt[NG];
// CSR
__device__ int g_deg[NN];
__device__ int g_rowptr[NN + 1];
__device__ int g_cursor[NN];
__device__ int g_csrc[NE];
__device__ int g_bsum[512];
__device__ int g_boff[512];
// Pre-split fp16 B chunk images: 2 layers x 8 chunks x [64 k][136 n(pad)]
// chunks 0-3 = Wh (K 0..255), chunks 4-7 = Wl residual.
__device__ uint32_t g_Bp[2 * 8 * 4352];

// ---------------------------------------------------------------------------
// Helpers
// ---------------------------------------------------------------------------
__device__ __forceinline__ uint32_t smem_u32(const void* p) {
    uint32_t a;
    asm("{ .reg .u64 t; cvta.to.shared.u64 t, %1; cvt.u32.u64 %0, t; }"
        : "=r"(a) : "l"(p));
    return a;
}

__device__ __forceinline__ uint32_t pack_h2(__half lo, __half hi) {
    return ((uint32_t)__half_as_ushort(hi) << 16) | __half_as_ushort(lo);
}

__device__ __forceinline__ void ldmatrix_x4(uint32_t r[4], uint32_t addr) {
    asm volatile("ldmatrix.sync.aligned.m8n8.x4.shared.b16 {%0,%1,%2,%3}, [%4];"
                 : "=r"(r[0]), "=r"(r[1]), "=r"(r[2]), "=r"(r[3]) : "r"(addr));
}

__device__ __forceinline__ void ldmatrix_x2t(uint32_t& b0, uint32_t& b1, uint32_t addr) {
    asm volatile("ldmatrix.sync.aligned.m8n8.x2.trans.shared.b16 {%0,%1}, [%2];"
                 : "=r"(b0), "=r"(b1) : "r"(addr));
}

__device__ __forceinline__ void mma_f16(float d[4], const uint32_t a[4],
                                        uint32_t b0, uint32_t b1) {
    asm volatile(
        "mma.sync.aligned.m16n8k16.row.col.f32.f16.f16.f32 "
        "{%0,%1,%2,%3}, {%4,%5,%6,%7}, {%8,%9}, {%0,%1,%2,%3};"
        : "+f"(d[0]), "+f"(d[1]), "+f"(d[2]), "+f"(d[3])
        : "r"(a[0]), "r"(a[1]), "r"(a[2]), "r"(a[3]), "r"(b0), "r"(b1));
}

// ---------------------------------------------------------------------------
// CSR build: degree histogram -> scan -> fill
// ---------------------------------------------------------------------------
__global__ void k_deg(const int* __restrict__ ei, int E) {
    int e = blockIdx.x * blockDim.x + threadIdx.x;
    if (e < E) atomicAdd(&g_deg[ei[E + e]], 1);
}

__global__ void k_scan1(int N) {
    __shared__ int s[256];
    int idx = blockIdx.x * 256 + threadIdx.x;
    int v = (idx < N) ? g_deg[idx] : 0;
    s[threadIdx.x] = v;
    __syncthreads();
    for (int off = 128; off > 0; off >>= 1) {
        if (threadIdx.x < off) s[threadIdx.x] += s[threadIdx.x + off];
        __syncthreads();
    }
    if (threadIdx.x == 0) g_bsum[blockIdx.x] = s[0];
}

__global__ void k_scan2(int nb, int E) {
    int lane = threadIdx.x;  // one warp
    int run = 0;
    for (int base = 0; base < nb; base += 32) {
        int i = base + lane;
        int orig = (i < nb) ? g_bsum[i] : 0;
        int v = orig;
#pragma unroll
        for (int off = 1; off < 32; off <<= 1) {
            int t = __shfl_up_sync(0xffffffff, v, off);
            if (lane >= off) v += t;
        }
        if (i < nb) g_boff[i] = run + v - orig;
        run += __shfl_sync(0xffffffff, v, 31);
    }
    if (lane == 0) g_rowptr[NN] = E;
}

__global__ void k_scan3(int N) {
    __shared__ int s[256];
    int t = threadIdx.x;
    int idx = blockIdx.x * 256 + t;
    int v = (idx < N) ? g_deg[idx] : 0;
    s[t] = v;
    __syncthreads();
#pragma unroll
    for (int off = 1; off < 256; off <<= 1) {
        int add = (t >= off) ? s[t - off] : 0;
        __syncthreads();
        s[t] += add;
        __syncthreads();
    }
    if (idx < N) {
        int ex = s[t] - v + g_boff[blockIdx.x];
        g_rowptr[idx] = ex;
        g_cursor[idx] = ex;
    }
}

__global__ void k_fill(const int* __restrict__ ei, int E) {
    int e = blockIdx.x * blockDim.x + threadIdx.x;
    if (e < E) {
        int s = ei[e];
        int d = ei[E + e];
        int pos = atomicAdd(&g_cursor[d], 1);
        g_csrc[pos] = s;
    }
}

// ---------------------------------------------------------------------------
// Scalar aggregation for layer 1 + inverse degree
// ---------------------------------------------------------------------------
__global__ void k_aggx(const float* __restrict__ x, int N) {
    int n = blockIdx.x * blockDim.x + threadIdx.x;
    if (n < N) {
        int beg = g_rowptr[n], end = g_rowptr[n + 1];
        float s = 0.0f;
        for (int i = beg; i < end; i++) s += __ldg(&x[g_csrc[i]]);
        g_aggx[n] = s;
        g_inv[n] = 1.0f / fmaxf((float)(end - beg), 1.0f);
    }
}

__global__ void k_gcnt(const int* __restrict__ batch, int N) {
    int t = blockIdx.x * blockDim.x + threadIdx.x;
    int n0 = t * 32;
    if (n0 >= N) return;
    int ne = min(n0 + 32, N);
    int cur = batch[n0];
    float c = 0.0f;
    for (int n = n0; n < ne; n++) {
        int b = batch[n];
        if (b != cur) { atomicAdd(&g_gcnt[cur], c); c = 0.0f; cur = b; }
        c += 1.0f;
    }
    atomicAdd(&g_gcnt[cur], c);
}

// ---------------------------------------------------------------------------
// Layer 1 (exact fp32, rank-2), half2 output
// ---------------------------------------------------------------------------
__global__ void k_layer1(const float* __restrict__ x,
                         const float* __restrict__ W1l,
                         const float* __restrict__ W1r,
                         const float* __restrict__ b1, int N) {
    int i = blockIdx.x * blockDim.x + threadIdx.x;
    if (i < N * (HID / 2)) {
        int n = i >> 6;
        int j = (i & 63) * 2;
        float mean = g_aggx[n] * g_inv[n];
        float xv = __ldg(&x[n]);
        float2 wl = *(const float2*)(W1l + j);
        float2 wr = *(const float2*)(W1r + j);
        float2 bb = *(const float2*)(b1 + j);
        float v0 = fmaxf(fmaf(mean, wl.x, fmaf(xv, wr.x, bb.x)), 0.0f);
        float v1 = fmaxf(fmaf(mean, wl.y, fmaf(xv, wr.y, bb.y)), 0.0f);
        ((__half2*)g_h1h)[i] = __floats2half2_rn(v0, v1);
    }
}

// ---------------------------------------------------------------------------
// CSR gather: 2 nodes/warp, 16 lanes/node, uint4 loads; stores fp16 MEAN.
// ---------------------------------------------------------------------------
__global__ void k_gather(const __half* __restrict__ h, int N) {
    int gt = blockIdx.x * blockDim.x + threadIdx.x;
    int node = gt >> 4;        // half-warp per node
    int lane = gt & 15;        // 16 B per lane covers the 256 B row
    if (node >= N) return;
    int beg = g_rowptr[node], end = g_rowptr[node + 1];
    float a0 = 0.f, a1 = 0.f, a2 = 0.f, a3 = 0.f;
    float a4 = 0.f, a5 = 0.f, a6 = 0.f, a7 = 0.f;
    int i = beg;
    for (; i + 1 < end; i += 2) {
        int s0 = g_csrc[i], s1 = g_csrc[i + 1];
        uint4 u0 = __ldg((const uint4*)(h + (size_t)s0 * HID) + lane);
        uint4 u1 = __ldg((const uint4*)(h + (size_t)s1 * HID) + lane);
        float2 p;
        p = __half22float2(*(__half2*)&u0.x); a0 += p.x; a1 += p.y;
        p = __half22float2(*(__half2*)&u0.y); a2 += p.x; a3 += p.y;
        p = __half22float2(*(__half2*)&u0.z); a4 += p.x; a5 += p.y;
        p = __half22float2(*(__half2*)&u0.w); a6 += p.x; a7 += p.y;
        p = __half22float2(*(__half2*)&u1.x); a0 += p.x; a1 += p.y;
        p = __half22float2(*(__half2*)&u1.y); a2 += p.x; a3 += p.y;
        p = __half22float2(*(__half2*)&u1.z); a4 += p.x; a5 += p.y;
        p = __half22float2(*(__half2*)&u1.w); a6 += p.x; a7 += p.y;
    }
    if (i < end) {
        int s0 = g_csrc[i];
        uint4 u0 = __ldg((const uint4*)(h + (size_t)s0 * HID) + lane);
        float2 p;
        p = __half22float2(*(__half2*)&u0.x); a0 += p.x; a1 += p.y;
        p = __half22float2(*(__half2*)&u0.y); a2 += p.x; a3 += p.y;
        p = __half22float2(*(__half2*)&u0.z); a4 += p.x; a5 += p.y;
        p = __half22float2(*(__half2*)&u0.w); a6 += p.x; a7 += p.y;
    }
    float inv = g_inv[node];
    uint4 o;
    *(__half2*)&o.x = __floats2half2_rn(a0 * inv, a1 * inv);
    *(__half2*)&o.y = __floats2half2_rn(a2 * inv, a3 * inv);
    *(__half2*)&o.z = __floats2half2_rn(a4 * inv, a5 * inv);
    *(__half2*)&o.w = __floats2half2_rn(a6 * inv, a7 * inv);
    ((uint4*)(g_meanh + (size_t)node * HID))[lane] = o;
}

// ---------------------------------------------------------------------------
// Weight prep: fp16 2-term split, chunk images [64 k][136 n(pad)].
// chunks 0-3 = Wh (K 0..255), 4-7 = Wl = fp16(W - Wh).
// W'[k][n]: k<128 -> Wl_model, else Wr_model.
// ---------------------------------------------------------------------------
__global__ void k_prepB(const float* __restrict__ Wl,
                        const float* __restrict__ Wr, int layer) {
    int t = blockIdx.x * blockDim.x + threadIdx.x;
    if (t >= 8 * 64 * 64) return;
    int ci = t >> 12;
    int rem = t & 4095;
    int k = rem >> 6;
    int np = rem & 63;
    int n = np * 2;
    int kk = (ci & 3) * 64 + k;
    float w0 = (kk < 128) ? Wl[kk * HID + n] : Wr[(kk - 128) * HID + n];
    float w1 = (kk < 128) ? Wl[kk * HID + n + 1] : Wr[(kk - 128) * HID + n + 1];
    __half p0, p1;
    if (ci < 4) {
        p0 = __float2half_rn(w0);
        p1 = __float2half_rn(w1);
    } else {
        __half h0 = __float2half_rn(w0), h1 = __float2half_rn(w1);
        p0 = __float2half_rn(w0 - __half2float(h0));
        p1 = __float2half_rn(w1 - __half2float(h1));
    }
    g_Bp[layer * 34816 + ci * 4352 + k * 68 + np] = pack_h2(p0, p1);
}

// ---------------------------------------------------------------------------
// Fused SAGE GEMM, fp16 mma, 2-term weight split (K_eff = 512):
//   hout = relu( [mean | hin] @ (Wh + Wl) + b )  -> fp16 out
// 64x128 tile / block, 256 threads, occ 3. Full cp.async staging:
// smem: A[64][264 fp16] (33792B) | B dbuf (2x17408B) = 68608B total
// ---------------------------------------------------------------------------
#define AP 528          // A row stride bytes (264 fp16, odd 16B-stride)
#define BP 272          // B row stride bytes (136 fp16)
#define SM_B  33792
#define BCH   17408
#define SMEM_GEMM (33792 + 2 * 17408)

__device__ __forceinline__ void prefB(uint32_t smdst, const uint32_t* src, int tid) {
#pragma unroll
    for (int m = 0; m < 5; m++) {
        int i = tid + m * 256;
        if (i < 1088)
            asm volatile("cp.async.cg.shared.global [%0], [%1], 16;"
                         :: "r"(smdst + i * 16), "l"((const uint4*)src + i) : "memory");
    }
    asm volatile("cp.async.commit_group;" ::: "memory");
}

__global__ __launch_bounds__(256, 3)
void k_gemm(const __half* __restrict__ hin, __half* __restrict__ hout,
            const float* __restrict__ bias, int layer, int N) {
    extern __shared__ char sm[];
    uint32_t smb = smem_u32(sm);
    int tid = threadIdx.x;
    int lane = tid & 31;
    int wid = tid >> 5;
    int n0 = blockIdx.x * 64;
    const uint32_t* Bpl = g_Bp + layer * 34816;

    // --- Stage A via cp.async: row r = [mean(node) | hin(node)], 512 B/row ---
    // 64 rows x 32 chunks of 16 B = 2048 chunks.
#pragma unroll
    for (int m = 0; m < 8; m++) {
        int idx = tid + m * 256;       // 0..2047
        int r = idx >> 5;              // 0..63
        int c32 = idx & 31;            // 32 x 16B chunks per row
        int node = n0 + r;
        uint32_t dst = smb + (uint32_t)(r * AP + c32 * 16);
        if (node < N) {
            const char* src = (c32 < 16)
                ? (const char*)(g_meanh + (size_t)node * HID) + c32 * 16
                : (const char*)(hin + (size_t)node * HID) + (c32 - 16) * 16;
            asm volatile("cp.async.cg.shared.global [%0], [%1], 16;"
                         :: "r"(dst), "l"(src) : "memory");
        } else {
            asm volatile("st.shared.v4.b32 [%0], {%1,%1,%1,%1};"
                         :: "r"(dst), "r"(0u) : "memory");
        }
    }
    asm volatile("cp.async.commit_group;" ::: "memory");

    // B chunk 0,1 prefetch (commit groups: A, c0, c1)
    prefB(smb + SM_B, Bpl, tid);
    prefB(smb + SM_B + BCH, Bpl + 4352, tid);

    float acc[2][4][4];
#pragma unroll
    for (int s = 0; s < 2; s++)
#pragma unroll
        for (int nt = 0; nt < 4; nt++)
#pragma unroll
            for (int q = 0; q < 4; q++) acc[s][nt][q] = 0.0f;

    int wr = wid & 1;          // 2 row groups of 32
    int wc = wid >> 1;         // 4 col groups of 32
    int a_r = lane & 15;
    int a_c8 = (lane >> 4) << 3;
    int b_r = lane & 15;

    for (int ci = 0; ci < 8; ci++) {
        if (ci >= 1 && ci < 7)
            prefB(smb + SM_B + ((ci + 1) & 1) * BCH, Bpl + (ci + 1) * 4352, tid);
        if (ci < 7) asm volatile("cp.async.wait_group 1;" ::: "memory");
        else        asm volatile("cp.async.wait_group 0;" ::: "memory");
        __syncthreads();

        int kc = ci & 3;                 // Wh: 0-3, Wl: 4-7 reuse same A cols
        int acol0 = kc * 64;
        uint32_t bbuf = smb + SM_B + (uint32_t)(ci & 1) * BCH;

#pragma unroll
        for (int ks = 0; ks < 4; ks++) {
            int k0 = acol0 + ks * 16;
            uint32_t a0[4], a1[4];
            uint32_t addr0 = smb + (uint32_t)((wr * 32 + a_r) * AP + (k0 + a_c8) * 2);
            ldmatrix_x4(a0, addr0);
            ldmatrix_x4(a1, addr0 + 16 * AP);
            uint32_t bbase = bbuf + (uint32_t)((ks * 16 + b_r) * BP + wc * 64);
#pragma unroll
            for (int nt = 0; nt < 4; nt++) {
                uint32_t b0, b1;
                ldmatrix_x2t(b0, b1, bbase + nt * 16);
                mma_f16(acc[0][nt], a0, b0, b1);
                mma_f16(acc[1][nt], a1, b0, b1);
            }
        }
        __syncthreads();
    }

    // --- Epilogue: bias + relu -> fp16 ---
    int qr = lane >> 2;
    int qc = (lane & 3) * 2;
#pragma unroll
    for (int s = 0; s < 2; s++) {
        int mb = n0 + wr * 32 + s * 16;
#pragma unroll
        for (int nt = 0; nt < 4; nt++) {
            int col = wc * 32 + nt * 8 + qc;
            float2 bv = *(const float2*)(bias + col);
            int mlo = mb + qr;
            int mhi = mlo + 8;
            if (mlo < N) {
                float o0 = fmaxf(acc[s][nt][0] + bv.x, 0.f);
                float o1 = fmaxf(acc[s][nt][1] + bv.y, 0.f);
                *(__half2*)(hout + (size_t)mlo * HID + col) = __floats2half2_rn(o0, o1);
            }
            if (mhi < N) {
                float o0 = fmaxf(acc[s][nt][2] + bv.x, 0.f);
                float o1 = fmaxf(acc[s][nt][3] + bv.y, 0.f);
                *(__half2*)(hout + (size_t)mhi * HID + col) = __floats2half2_rn(o0, o1);
            }
        }
    }
}

// ---------------------------------------------------------------------------
// Mean pool: run-length compressed atomics (batch sorted), fp16 input
// ---------------------------------------------------------------------------
__global__ void k_pool(const __half* __restrict__ h,
                       const int* __restrict__ batch, int N) {
    int j = threadIdx.x;
    int n0 = blockIdx.x * 64;
    if (n0 >= N) return;
    int ne = min(n0 + 64, N);
    int cur = batch[n0];
    float acc = 0.0f;
    for (int n = n0; n < ne; n++) {
        int b = batch[n];
        if (b != cur) {
            atomicAdd(&g_pool[cur * HID + j], acc);
            acc = 0.0f;
            cur = b;
        }
        acc += __half2float(h[(size_t)n * HID + j]);
    }
    atomicAdd(&g_pool[cur * HID + j], acc);
}

// ---------------------------------------------------------------------------
// Head: logits = (pool/gcnt) @ Wfc + bfc ; log_softmax
// ---------------------------------------------------------------------------
__global__ void k_head(const float* __restrict__ Wfc,
                       const float* __restrict__ bfc,
                       float* __restrict__ out) {
    __shared__ float lg[NG][NC];
    int t = threadIdx.x;
    if (t < NG * NC) {
        int g = t / NC;
        int c = t % NC;
        float ginv = 1.0f / fmaxf(g_gcnt[g], 1.0f);
        float s = __ldg(&bfc[c]);
        for (int k = 0; k < HID; k++)
            s = fmaf(g_pool[g * HID + k] * ginv, __ldg(&Wfc[k * NC + c]), s);
        lg[g][c] = s;
    }
    __syncthreads();
    if (t < NG) {
        float m = -1e30f;
        for (int c = 0; c < NC; c++) m = fmaxf(m, lg[t][c]);
        float se = 0.0f;
        for (int c = 0; c < NC; c++) se += expf(lg[t][c] - m);
        float lse = m + logf(se);
        for (int c = 0; c < NC; c++) out[t * NC + c] = lg[t][c] - lse;
    }
}

// ---------------------------------------------------------------------------
extern "C" void kernel_launch(void* const* d_in, const int* in_sizes, int n_in,
                              void* d_out, int out_size) {
    const float* x   = (const float*)d_in[0];
    const int* ei    = (const int*)d_in[1];
    const int* batch = (const int*)d_in[2];
    const float* W1l = (const float*)d_in[3];
    const float* W1r = (const float*)d_in[4];
    const float* b1  = (const float*)d_in[5];
    const float* W2l = (const float*)d_in[6];
    const float* W2r = (const float*)d_in[7];
    const float* b2  = (const float*)d_in[8];
    const float* W3l = (const float*)d_in[9];
    const float* W3r = (const float*)d_in[10];
    const float* b3  = (const float*)d_in[11];
    const float* Wfc = (const float*)d_in[12];
    const float* bfc = (const float*)d_in[13];
    float* out = (float*)d_out;

    int N = in_sizes[0];
    int E = in_sizes[1] / 2;
    int nb = (N + 255) / 256;

    void *p_deg, *p_gcnt, *p_pool, *p_h1, *p_h2;
    cudaGetSymbolAddress(&p_deg, g_deg);
    cudaGetSymbolAddress(&p_gcnt, g_gcnt);
    cudaGetSymbolAddress(&p_pool, g_pool);
    cudaGetSymbolAddress(&p_h1, g_h1h);
    cudaGetSymbolAddress(&p_h2, g_h2h);

    cudaFuncSetAttribute(k_gemm, cudaFuncAttributeMaxDynamicSharedMemorySize, SMEM_GEMM);

    cudaMemsetAsync(p_deg, 0, (size_t)N * 4);
    cudaMemsetAsync(p_gcnt, 0, NG * 4);
    cudaMemsetAsync(p_pool, 0, NG * HID * 4);

    // CSR build
    k_deg<<<(E + 255) / 256, 256>>>(ei, E);
    k_scan1<<<nb, 256>>>(N);
    k_scan2<<<1, 32>>>(nb, E);
    k_scan3<<<nb, 256>>>(N);
    k_fill<<<(E + 255) / 256, 256>>>(ei, E);

    // Prep + layer 1
    k_aggx<<<(N + 255) / 256, 256>>>(x, N);
    k_gcnt<<<((N + 31) / 32 + 255) / 256, 256>>>(batch, N);
    k_prepB<<<128, 256>>>(W2l, W2r, 0);
    k_prepB<<<128, 256>>>(W3l, W3r, 1);
    k_layer1<<<(N * (HID / 2) + 255) / 256, 256>>>(x, W1l, W1r, b1, N);

    int gat_blocks = (N * 16 + 255) / 256;
    int gemm_blocks = (N + 63) / 64;

    // Layer 2
    k_gather<<<gat_blocks, 256>>>((const __half*)p_h1, N);
    k_gemm<<<gemm_blocks, 256, SMEM_GEMM>>>((const __half*)p_h1, (__half*)p_h2, b2, 0, N);

    // Layer 3
    k_gather<<<gat_blocks, 256>>>((const __half*)p_h2, N);
    k_gemm<<<gemm_blocks, 256, SMEM_GEMM>>>((const __half*)p_h2, (__half*)p_h1, b3, 1, N);

    // Pool + head
    k_pool<<<(N + 63) / 64, 128>>>((const __half*)p_h1, batch, N);
    k_head<<<1, 640>>>(Wfc, bfc, out);
}

// round 10
// speedup vs baseline: 3.9528x; 1.0320x over previous
#include <cuda_runtime.h>
#include <cuda_fp16.h>
#include <cstdint>

#define NN 100000
#define NE 1600000
#define HID 128
#define NG 64
#define NC 10

// ---------------------------------------------------------------------------
// Persistent scratch (static __device__ arrays — no runtime allocation).
// ---------------------------------------------------------------------------
__device__ __half g_h1h[NN * HID];     // fp16 activations (ping)
__device__ __half g_h2h[NN * HID];     // fp16 activations (pong)
__device__ float g_inv[NN];
__device__ float g_pool[NG * HID];
__device__ float g_gcnt[NG];
// CSR
__device__ int g_deg[NN];
__device__ int g_rowptr[NN + 1];
__device__ int g_cursor[NN];
__device__ int g_csrc[NE];
__device__ int g_bsum[512];
__device__ int g_boff[512];
// Pre-split fp16 B chunk images: 2 layers x 8 chunks x [64 k][136 n(pad)]
// chunks 0-3 = Wh (K 0..255), chunks 4-7 = Wl residual.
__device__ uint32_t g_Bp[2 * 8 * 4352];

// ---------------------------------------------------------------------------
// Helpers
// ---------------------------------------------------------------------------
__device__ __forceinline__ uint32_t smem_u32(const void* p) {
    uint32_t a;
    asm("{ .reg .u64 t; cvta.to.shared.u64 t, %1; cvt.u32.u64 %0, t; }"
        : "=r"(a) : "l"(p));
    return a;
}

__device__ __forceinline__ uint32_t pack_h2(__half lo, __half hi) {
    return ((uint32_t)__half_as_ushort(hi) << 16) | __half_as_ushort(lo);
}

__device__ __forceinline__ void ldmatrix_x4(uint32_t r[4], uint32_t addr) {
    asm volatile("ldmatrix.sync.aligned.m8n8.x4.shared.b16 {%0,%1,%2,%3}, [%4];"
                 : "=r"(r[0]), "=r"(r[1]), "=r"(r[2]), "=r"(r[3]) : "r"(addr));
}

__device__ __forceinline__ void ldmatrix_x2t(uint32_t& b0, uint32_t& b1, uint32_t addr) {
    asm volatile("ldmatrix.sync.aligned.m8n8.x2.trans.shared.b16 {%0,%1}, [%2];"
                 : "=r"(b0), "=r"(b1) : "r"(addr));
}

__device__ __forceinline__ void mma_f16(float d[4], const uint32_t a[4],
                                        uint32_t b0, uint32_t b1) {
    asm volatile(
        "mma.sync.aligned.m16n8k16.row.col.f32.f16.f16.f32 "
        "{%0,%1,%2,%3}, {%4,%5,%6,%7}, {%8,%9}, {%0,%1,%2,%3};"
        : "+f"(d[0]), "+f"(d[1]), "+f"(d[2]), "+f"(d[3])
        : "r"(a[0]), "r"(a[1]), "r"(a[2]), "r"(a[3]), "r"(b0), "r"(b1));
}

// ---------------------------------------------------------------------------
// CSR build: degree histogram -> scan -> fill
// ---------------------------------------------------------------------------
__global__ void k_deg(const int* __restrict__ ei, int E) {
    int e = blockIdx.x * blockDim.x + threadIdx.x;
    if (e < E) atomicAdd(&g_deg[ei[E + e]], 1);
}

__global__ void k_scan1(int N) {
    __shared__ int s[256];
    int idx = blockIdx.x * 256 + threadIdx.x;
    int v = (idx < N) ? g_deg[idx] : 0;
    s[threadIdx.x] = v;
    __syncthreads();
    for (int off = 128; off > 0; off >>= 1) {
        if (threadIdx.x < off) s[threadIdx.x] += s[threadIdx.x + off];
        __syncthreads();
    }
    if (threadIdx.x == 0) g_bsum[blockIdx.x] = s[0];
}

__global__ void k_scan2(int nb, int E) {
    int lane = threadIdx.x;  // one warp
    int run = 0;
    for (int base = 0; base < nb; base += 32) {
        int i = base + lane;
        int orig = (i < nb) ? g_bsum[i] : 0;
        int v = orig;
#pragma unroll
        for (int off = 1; off < 32; off <<= 1) {
            int t = __shfl_up_sync(0xffffffff, v, off);
            if (lane >= off) v += t;
        }
        if (i < nb) g_boff[i] = run + v - orig;
        run += __shfl_sync(0xffffffff, v, 31);
    }
    if (lane == 0) g_rowptr[NN] = E;
}

__global__ void k_scan3(int N) {
    __shared__ int s[256];
    int t = threadIdx.x;
    int idx = blockIdx.x * 256 + t;
    int v = (idx < N) ? g_deg[idx] : 0;
    s[t] = v;
    __syncthreads();
#pragma unroll
    for (int off = 1; off < 256; off <<= 1) {
        int add = (t >= off) ? s[t - off] : 0;
        __syncthreads();
        s[t] += add;
        __syncthreads();
    }
    if (idx < N) {
        int ex = s[t] - v + g_boff[blockIdx.x];
        g_rowptr[idx] = ex;
        g_cursor[idx] = ex;
    }
}

__global__ void k_fill(const int* __restrict__ ei, int E) {
    int e = blockIdx.x * blockDim.x + threadIdx.x;
    if (e < E) {
        int s = ei[e];
        int d = ei[E + e];
        int pos = atomicAdd(&g_cursor[d], 1);
        g_csrc[pos] = s;
    }
}

__global__ void k_gcnt(const int* __restrict__ batch, int N) {
    int t = blockIdx.x * blockDim.x + threadIdx.x;
    int n0 = t * 32;
    if (n0 >= N) return;
    int ne = min(n0 + 32, N);
    int cur = batch[n0];
    float c = 0.0f;
    for (int n = n0; n < ne; n++) {
        int b = batch[n];
        if (b != cur) { atomicAdd(&g_gcnt[cur], c); c = 0.0f; cur = b; }
        c += 1.0f;
    }
    atomicAdd(&g_gcnt[cur], c);
}

// ---------------------------------------------------------------------------
// Fused CSR scalar aggregation + layer 1: warp per node.
// Also writes g_inv for later layers.
// ---------------------------------------------------------------------------
__global__ void k_layer1f(const float* __restrict__ x,
                          const float* __restrict__ W1l,
                          const float* __restrict__ W1r,
                          const float* __restrict__ b1, int N) {
    int wid = threadIdx.x >> 5;
    int lane = threadIdx.x & 31;
    int node = blockIdx.x * 8 + wid;
    if (node >= N) return;
    int beg = g_rowptr[node], end = g_rowptr[node + 1];
    float s = 0.0f;
    for (int i = beg + lane; i < end; i += 32) s += __ldg(&x[g_csrc[i]]);
#pragma unroll
    for (int off = 16; off > 0; off >>= 1)
        s += __shfl_xor_sync(0xffffffff, s, off);
    float inv = 1.0f / fmaxf((float)(end - beg), 1.0f);
    if (lane == 0) g_inv[node] = inv;
    float mean = s * inv;
    float xv = __ldg(&x[node]);
    int j = lane * 4;
    float4 wl = *(const float4*)(W1l + j);
    float4 wr = *(const float4*)(W1r + j);
    float4 bb = *(const float4*)(b1 + j);
    float v0 = fmaxf(fmaf(mean, wl.x, fmaf(xv, wr.x, bb.x)), 0.0f);
    float v1 = fmaxf(fmaf(mean, wl.y, fmaf(xv, wr.y, bb.y)), 0.0f);
    float v2 = fmaxf(fmaf(mean, wl.z, fmaf(xv, wr.z, bb.z)), 0.0f);
    float v3 = fmaxf(fmaf(mean, wl.w, fmaf(xv, wr.w, bb.w)), 0.0f);
    uint2 o;
    *(__half2*)&o.x = __floats2half2_rn(v0, v1);
    *(__half2*)&o.y = __floats2half2_rn(v2, v3);
    *(uint2*)(g_h1h + (size_t)node * HID + j) = o;
}

// ---------------------------------------------------------------------------
// Weight prep: fp16 2-term split, chunk images [64 k][136 n(pad)].
// chunks 0-3 = Wh (K 0..255), 4-7 = Wl = fp16(W - Wh).
// ---------------------------------------------------------------------------
__global__ void k_prepB(const float* __restrict__ Wl,
                        const float* __restrict__ Wr, int layer) {
    int t = blockIdx.x * blockDim.x + threadIdx.x;
    if (t >= 8 * 64 * 64) return;
    int ci = t >> 12;
    int rem = t & 4095;
    int k = rem >> 6;
    int np = rem & 63;
    int n = np * 2;
    int kk = (ci & 3) * 64 + k;
    float w0 = (kk < 128) ? Wl[kk * HID + n] : Wr[(kk - 128) * HID + n];
    float w1 = (kk < 128) ? Wl[kk * HID + n + 1] : Wr[(kk - 128) * HID + n + 1];
    __half p0, p1;
    if (ci < 4) {
        p0 = __float2half_rn(w0);
        p1 = __float2half_rn(w1);
    } else {
        __half h0 = __float2half_rn(w0), h1 = __float2half_rn(w1);
        p0 = __float2half_rn(w0 - __half2float(h0));
        p1 = __float2half_rn(w1 - __half2float(h1));
    }
    g_Bp[layer * 34816 + ci * 4352 + k * 68 + np] = pack_h2(p0, p1);
}

// ---------------------------------------------------------------------------
// FUSED gather + SAGE GEMM (fp16 mma, 2-term weight split, K_eff = 512):
//   A-tile row = [mean(node) | hin(node)]; mean gathered IN-KERNEL from CSR.
//   hout = relu( A @ (Wh + Wl) + b )  -> fp16
// 64x128 tile / block, 256 threads, occ 3.
// smem: A[64][264 fp16] (33792B) | B dbuf (2x17408B) = 68608B total
// ---------------------------------------------------------------------------
#define AP 528          // A row stride bytes (264 fp16, odd 16B-stride)
#define BP 272          // B row stride bytes (136 fp16)
#define SM_B  33792
#define BCH   17408
#define SMEM_GEMM (33792 + 2 * 17408)

__device__ __forceinline__ void prefB(uint32_t smdst, const uint32_t* src, int tid) {
#pragma unroll
    for (int m = 0; m < 5; m++) {
        int i = tid + m * 256;
        if (i < 1088)
            asm volatile("cp.async.cg.shared.global [%0], [%1], 16;"
                         :: "r"(smdst + i * 16), "l"((const uint4*)src + i) : "memory");
    }
    asm volatile("cp.async.commit_group;" ::: "memory");
}

__global__ __launch_bounds__(256, 3)
void k_gemm(const __half* __restrict__ hin, __half* __restrict__ hout,
            const float* __restrict__ bias, int layer, int N) {
    extern __shared__ char sm[];
    uint32_t smb = smem_u32(sm);
    int tid = threadIdx.x;
    int lane = tid & 31;
    int wid = tid >> 5;
    int n0 = blockIdx.x * 64;
    const uint32_t* Bpl = g_Bp + layer * 34816;

    // --- Stage hin half-rows via cp.async: 64 rows x 16 chunks = 1024 ---
#pragma unroll
    for (int m = 0; m < 4; m++) {
        int idx = tid + m * 256;
        int r = idx >> 4;
        int c16 = idx & 15;
        int node = n0 + r;
        uint32_t dst = smb + (uint32_t)(r * AP + 256 + c16 * 16);
        if (node < N) {
            const char* src = (const char*)(hin + (size_t)node * HID) + c16 * 16;
            asm volatile("cp.async.cg.shared.global [%0], [%1], 16;"
                         :: "r"(dst), "l"(src) : "memory");
        } else {
            asm volatile("st.shared.v4.b32 [%0], {%1,%1,%1,%1};"
                         :: "r"(dst), "r"(0u) : "memory");
        }
    }
    asm volatile("cp.async.commit_group;" ::: "memory");

    // B chunk 0,1 prefetch (commit groups: hin, c0, c1)
    prefB(smb + SM_B, Bpl, tid);
    prefB(smb + SM_B + BCH, Bpl + 4352, tid);

    // --- In-kernel CSR gather of neighbor means into A cols 0..127 ---
    // Half-warp per node, 4 passes: node_local = wid*8 + pass*2 + (lane>>4)
    {
        int hw = lane >> 4;
        int sl = lane & 15;     // 16B chunk within the 256B mean half-row
#pragma unroll
        for (int pass = 0; pass < 4; pass++) {
            int nl = wid * 8 + pass * 2 + hw;
            int node = n0 + nl;
            float a0 = 0.f, a1 = 0.f, a2 = 0.f, a3 = 0.f;
            float a4 = 0.f, a5 = 0.f, a6 = 0.f, a7 = 0.f;
            float inv = 1.0f;
            if (node < N) {
                int beg = g_rowptr[node], end = g_rowptr[node + 1];
                inv = g_inv[node];
                int i = beg;
                for (; i + 1 < end; i += 2) {
                    int s0 = g_csrc[i], s1 = g_csrc[i + 1];
                    uint4 u0 = __ldg((const uint4*)(hin + (size_t)s0 * HID) + sl);
                    uint4 u1 = __ldg((const uint4*)(hin + (size_t)s1 * HID) + sl);
                    float2 p;
                    p = __half22float2(*(__half2*)&u0.x); a0 += p.x; a1 += p.y;
                    p = __half22float2(*(__half2*)&u0.y); a2 += p.x; a3 += p.y;
                    p = __half22float2(*(__half2*)&u0.z); a4 += p.x; a5 += p.y;
                    p = __half22float2(*(__half2*)&u0.w); a6 += p.x; a7 += p.y;
                    p = __half22float2(*(__half2*)&u1.x); a0 += p.x; a1 += p.y;
                    p = __half22float2(*(__half2*)&u1.y); a2 += p.x; a3 += p.y;
                    p = __half22float2(*(__half2*)&u1.z); a4 += p.x; a5 += p.y;
                    p = __half22float2(*(__half2*)&u1.w); a6 += p.x; a7 += p.y;
                }
                if (i < end) {
                    int s0 = g_csrc[i];
                    uint4 u0 = __ldg((const uint4*)(hin + (size_t)s0 * HID) + sl);
                    float2 p;
                    p = __half22float2(*(__half2*)&u0.x); a0 += p.x; a1 += p.y;
                    p = __half22float2(*(__half2*)&u0.y); a2 += p.x; a3 += p.y;
                    p = __half22float2(*(__half2*)&u0.z); a4 += p.x; a5 += p.y;
                    p = __half22float2(*(__half2*)&u0.w); a6 += p.x; a7 += p.y;
                }
            }
            uint4 o;
            *(__half2*)&o.x = __floats2half2_rn(a0 * inv, a1 * inv);
            *(__half2*)&o.y = __floats2half2_rn(a2 * inv, a3 * inv);
            *(__half2*)&o.z = __floats2half2_rn(a4 * inv, a5 * inv);
            *(__half2*)&o.w = __floats2half2_rn(a6 * inv, a7 * inv);
            uint32_t dst = smb + (uint32_t)(nl * AP + sl * 16);
            asm volatile("st.shared.v4.b32 [%0], {%1,%2,%3,%4};"
                         :: "r"(dst), "r"(o.x), "r"(o.y), "r"(o.z), "r"(o.w)
                         : "memory");
        }
    }

    float acc[2][4][4];
#pragma unroll
    for (int s = 0; s < 2; s++)
#pragma unroll
        for (int nt = 0; nt < 4; nt++)
#pragma unroll
            for (int q = 0; q < 4; q++) acc[s][nt][q] = 0.0f;

    int wr = wid & 1;          // 2 row groups of 32
    int wc = wid >> 1;         // 4 col groups of 32
    int a_r = lane & 15;
    int a_c8 = (lane >> 4) << 3;
    int b_r = lane & 15;

    for (int ci = 0; ci < 8; ci++) {
        if (ci >= 1 && ci < 7)
            prefB(smb + SM_B + ((ci + 1) & 1) * BCH, Bpl + (ci + 1) * 4352, tid);
        if (ci < 7) asm volatile("cp.async.wait_group 1;" ::: "memory");
        else        asm volatile("cp.async.wait_group 0;" ::: "memory");
        __syncthreads();

        int kc = ci & 3;                 // Wh: 0-3, Wl: 4-7 reuse same A cols
        int acol0 = kc * 64;
        uint32_t bbuf = smb + SM_B + (uint32_t)(ci & 1) * BCH;

#pragma unroll
        for (int ks = 0; ks < 4; ks++) {
            int k0 = acol0 + ks * 16;
            uint32_t a0[4], a1[4];
            uint32_t addr0 = smb + (uint32_t)((wr * 32 + a_r) * AP + (k0 + a_c8) * 2);
            ldmatrix_x4(a0, addr0);
            ldmatrix_x4(a1, addr0 + 16 * AP);
            uint32_t bbase = bbuf + (uint32_t)((ks * 16 + b_r) * BP + wc * 64);
#pragma unroll
            for (int nt = 0; nt < 4; nt++) {
                uint32_t b0, b1;
                ldmatrix_x2t(b0, b1, bbase + nt * 16);
                mma_f16(acc[0][nt], a0, b0, b1);
                mma_f16(acc[1][nt], a1, b0, b1);
            }
        }
        __syncthreads();
    }

    // --- Epilogue: bias + relu -> fp16 ---
    int qr = lane >> 2;
    int qc = (lane & 3) * 2;
#pragma unroll
    for (int s = 0; s < 2; s++) {
        int mb = n0 + wr * 32 + s * 16;
#pragma unroll
        for (int nt = 0; nt < 4; nt++) {
            int col = wc * 32 + nt * 8 + qc;
            float2 bv = *(const float2*)(bias + col);
            int mlo = mb + qr;
            int mhi = mlo + 8;
            if (mlo < N) {
                float o0 = fmaxf(acc[s][nt][0] + bv.x, 0.f);
                float o1 = fmaxf(acc[s][nt][1] + bv.y, 0.f);
                *(__half2*)(hout + (size_t)mlo * HID + col) = __floats2half2_rn(o0, o1);
            }
            if (mhi < N) {
                float o0 = fmaxf(acc[s][nt][2] + bv.x, 0.f);
                float o1 = fmaxf(acc[s][nt][3] + bv.y, 0.f);
                *(__half2*)(hout + (size_t)mhi * HID + col) = __floats2half2_rn(o0, o1);
            }
        }
    }
}

// ---------------------------------------------------------------------------
// Mean pool: run-length compressed atomics (batch sorted), fp16 input
// ---------------------------------------------------------------------------
__global__ void k_pool(const __half* __restrict__ h,
                       const int* __restrict__ batch, int N) {
    int j = threadIdx.x;
    int n0 = blockIdx.x * 64;
    if (n0 >= N) return;
    int ne = min(n0 + 64, N);
    int cur = batch[n0];
    float acc = 0.0f;
    for (int n = n0; n < ne; n++) {
        int b = batch[n];
        if (b != cur) {
            atomicAdd(&g_pool[cur * HID + j], acc);
            acc = 0.0f;
            cur = b;
        }
        acc += __half2float(h[(size_t)n * HID + j]);
    }
    atomicAdd(&g_pool[cur * HID + j], acc);
}

// ---------------------------------------------------------------------------
// Head: logits = (pool/gcnt) @ Wfc + bfc ; log_softmax
// ---------------------------------------------------------------------------
__global__ void k_head(const float* __restrict__ Wfc,
                       const float* __restrict__ bfc,
                       float* __restrict__ out) {
    __shared__ float lg[NG][NC];
    int t = threadIdx.x;
    if (t < NG * NC) {
        int g = t / NC;
        int c = t % NC;
        float ginv = 1.0f / fmaxf(g_gcnt[g], 1.0f);
        float s = __ldg(&bfc[c]);
        for (int k = 0; k < HID; k++)
            s = fmaf(g_pool[g * HID + k] * ginv, __ldg(&Wfc[k * NC + c]), s);
        lg[g][c] = s;
    }
    __syncthreads();
    if (t < NG) {
        float m = -1e30f;
        for (int c = 0; c < NC; c++) m = fmaxf(m, lg[t][c]);
        float se = 0.0f;
        for (int c = 0; c < NC; c++) se += expf(lg[t][c] - m);
        float lse = m + logf(se);
        for (int c = 0; c < NC; c++) out[t * NC + c] = lg[t][c] - lse;
    }
}

// ---------------------------------------------------------------------------
extern "C" void kernel_launch(void* const* d_in, const int* in_sizes, int n_in,
                              void* d_out, int out_size) {
    const float* x   = (const float*)d_in[0];
    const int* ei    = (const int*)d_in[1];
    const int* batch = (const int*)d_in[2];
    const float* W1l = (const float*)d_in[3];
    const float* W1r = (const float*)d_in[4];
    const float* b1  = (const float*)d_in[5];
    const float* W2l = (const float*)d_in[6];
    const float* W2r = (const float*)d_in[7];
    const float* b2  = (const float*)d_in[8];
    const float* W3l = (const float*)d_in[9];
    const float* W3r = (const float*)d_in[10];
    const float* b3  = (const float*)d_in[11];
    const float* Wfc = (const float*)d_in[12];
    const float* bfc = (const float*)d_in[13];
    float* out = (float*)d_out;

    int N = in_sizes[0];
    int E = in_sizes[1] / 2;
    int nb = (N + 255) / 256;

    void *p_deg, *p_gcnt, *p_pool, *p_h1, *p_h2;
    cudaGetSymbolAddress(&p_deg, g_deg);
    cudaGetSymbolAddress(&p_gcnt, g_gcnt);
    cudaGetSymbolAddress(&p_pool, g_pool);
    cudaGetSymbolAddress(&p_h1, g_h1h);
    cudaGetSymbolAddress(&p_h2, g_h2h);

    cudaFuncSetAttribute(k_gemm, cudaFuncAttributeMaxDynamicSharedMemorySize, SMEM_GEMM);

    cudaMemsetAsync(p_deg, 0, (size_t)N * 4);
    cudaMemsetAsync(p_gcnt, 0, NG * 4);
    cudaMemsetAsync(p_pool, 0, NG * HID * 4);

    // CSR build
    k_deg<<<(E + 255) / 256, 256>>>(ei, E);
    k_scan1<<<nb, 256>>>(N);
    k_scan2<<<1, 32>>>(nb, E);
    k_scan3<<<nb, 256>>>(N);
    k_fill<<<(E + 255) / 256, 256>>>(ei, E);

    // Prep + layer 1 (fused CSR scalar agg + transform)
    k_gcnt<<<((N + 31) / 32 + 255) / 256, 256>>>(batch, N);
    k_prepB<<<128, 256>>>(W2l, W2r, 0);
    k_prepB<<<128, 256>>>(W3l, W3r, 1);
    k_layer1f<<<(N + 7) / 8, 256>>>(x, W1l, W1r, b1, N);

    int gemm_blocks = (N + 63) / 64;

    // Layer 2 (fused gather+gemm)
    k_gemm<<<gemm_blocks, 256, SMEM_GEMM>>>((const __half*)p_h1, (__half*)p_h2, b2, 0, N);

    // Layer 3 (fused gather+gemm)
    k_gemm<<<gemm_blocks, 256, SMEM_GEMM>>>((const __half*)p_h2, (__half*)p_h1, b3, 1, N);

    // Pool + head
    k_pool<<<(N + 63) / 64, 128>>>((const __half*)p_h1, batch, N);
    k_head<<<1, 640>>>(Wfc, bfc, out);
}